// round 14
// baseline (speedup 1.0000x reference)
#include <cuda_runtime.h>
#include <cuda_bf16.h>
#include <cuda_fp16.h>
#include <math.h>
#include <stdint.h>

// Problem constants
#define BB 8
#define TT 1024
#define DI 80
#define DD 256
#define HH 4
#define DKK 64
#define FFD 2048
#define NL 6
#define ROWS (BB*TT)        // 8192
#define SCALE 0.125f
#define EPSN 0.25f

// -------- scratch (static device globals) ----------
__device__ float g_x[ROWS*DD];
__device__ float g_qkv[ROWS*3*DD];      // only Q third written/read now
__device__ float g_pe[TT*DD];
__device__ __half g_bd[BB*HH*TT*TT];    // pre-shifted rel-pos term (fp16, 64MB)

// fp16 activation buffers
__device__ __half g_xa[ROWS*DD];
__device__ __half g_ta[ROWS*DD];
__device__ __half g_ha[ROWS*FFD];
// fp16 weight hi/lo splits
__device__ __half g_wqkvh[NL*3*DD*DD], g_wqkvl[NL*3*DD*DD];
__device__ __half g_wouth[NL*DD*DD],   g_woutl[NL*DD*DD];
__device__ __half g_wf1h[NL*FFD*DD],   g_wf1l[NL*FFD*DD];
__device__ __half g_wf2h[NL*DD*FFD],   g_wf2l[NL*DD*FFD];
// bf16 splits for attention-score path
__device__ __nv_bfloat16 g_qvh[BB*HH*TT*DKK], g_qvl[BB*HH*TT*DKK];
__device__ __nv_bfloat16 g_kh[BB*HH*TT*DKK],  g_kl[BB*HH*TT*DKK];
__device__ __nv_bfloat16 g_vh[BB*HH*TT*DKK],  g_vl[BB*HH*TT*DKK];
__device__ __nv_bfloat16 g_ph[NL*HH*TT*DKK], g_pl[NL*HH*TT*DKK];   // all layers

// ===================== PTX helpers (arch-neutral, sm_80+) =================
__device__ __forceinline__ uint32_t smem_u32(const void* p) {
    uint32_t a;
    asm("{ .reg .u64 t; cvta.to.shared.u64 t, %1; cvt.u32.u64 %0, t; }" : "=r"(a) : "l"(p));
    return a;
}
#define CP_ASYNC16(sa, ga) asm volatile("cp.async.cg.shared.global [%0], [%1], 16;" :: "r"(sa), "l"(ga))
#define CP_COMMIT()        asm volatile("cp.async.commit_group;" ::: "memory")

__device__ __forceinline__ void ldmx4(uint32_t (&r)[4], uint32_t addr) {
    asm volatile("ldmatrix.sync.aligned.m8n8.x4.shared.b16 {%0,%1,%2,%3}, [%4];"
        : "=r"(r[0]), "=r"(r[1]), "=r"(r[2]), "=r"(r[3]) : "r"(addr));
}
__device__ __forceinline__ void mma_bf(float (&c)[4], const uint32_t (&a)[4],
                                       uint32_t b0, uint32_t b1) {
    asm volatile("mma.sync.aligned.m16n8k16.row.col.f32.bf16.bf16.f32 "
        "{%0,%1,%2,%3}, {%4,%5,%6,%7}, {%8,%9}, {%0,%1,%2,%3};"
        : "+f"(c[0]), "+f"(c[1]), "+f"(c[2]), "+f"(c[3])
        : "r"(a[0]), "r"(a[1]), "r"(a[2]), "r"(a[3]), "r"(b0), "r"(b1));
}
__device__ __forceinline__ void mma_hf(float (&c)[4], const uint32_t (&a)[4],
                                       uint32_t b0, uint32_t b1) {
    asm volatile("mma.sync.aligned.m16n8k16.row.col.f32.f16.f16.f32 "
        "{%0,%1,%2,%3}, {%4,%5,%6,%7}, {%8,%9}, {%0,%1,%2,%3};"
        : "+f"(c[0]), "+f"(c[1]), "+f"(c[2]), "+f"(c[3])
        : "r"(a[0]), "r"(a[1]), "r"(a[2]), "r"(a[3]), "r"(b0), "r"(b1));
}
__device__ __forceinline__ uint32_t packbf2(float a, float b) {
    __nv_bfloat162 t = __floats2bfloat162_rn(a, b);
    return *(uint32_t*)&t;
}
__device__ __forceinline__ float bflo(float v, float* hi) {
    __nv_bfloat16 h = __float2bfloat16(v);
    *hi = __bfloat162float(h);
    return v - *hi;
}
__device__ __forceinline__ void st_bf2(__nv_bfloat16* p, float a, float b) {
    __nv_bfloat162 t = __floats2bfloat162_rn(a, b);
    *(__nv_bfloat162*)p = t;
}
__device__ __forceinline__ void st_hf2(__half* p, float a, float b) {
    *(__half2*)p = __floats2half2_rn(a, b);
}

// ===================== fp16x2 mma.sync GEMM (linear layers) ===============
// K-chunk 64, PADK 72. M tile 128; N tile = (8/WM)*32.
#define PADK 72

template<int WM>
__global__ __launch_bounds__(256, 2) void mma_gemm(
    const __half* __restrict__ A,
    const __half* __restrict__ Bh, const __half* __restrict__ Bl,
    const float* __restrict__ bias, const float* __restrict__ resid,
    float* __restrict__ C, __half* __restrict__ Oa,
    const float* __restrict__ pvb,
    __nv_bfloat16* __restrict__ Qh, __nv_bfloat16* __restrict__ Ql,
    __nv_bfloat16* __restrict__ Kh, __nv_bfloat16* __restrict__ Kl,
    __nv_bfloat16* __restrict__ Vh, __nv_bfloat16* __restrict__ Vl,
    int K, int ldC, int ep)
{
    constexpr int NT     = (8 / WM) * 32;
    constexpr int TMW    = 128 / (WM * 16);
    constexpr int ATILE_E = 128 * PADK;
    constexpr int BTILE_E = NT * PADK;
    constexpr int STG    = (ATILE_E + 2 * BTILE_E) * 2;

    extern __shared__ __half sm[];
    int tid = threadIdx.x, lane = tid & 31, w = tid >> 5;
    int wm = w % WM, wn = w / WM;
    int m0 = blockIdx.y * 128, n0 = blockIdx.x * NT;
    const __half* gA  = A  + (size_t)m0 * K;
    const __half* gBh = Bh + (size_t)n0 * K;
    const __half* gBl = Bl + (size_t)n0 * K;

    float acc[TMW][4][4];
#pragma unroll
    for (int a = 0; a < TMW; a++)
#pragma unroll
        for (int b = 0; b < 4; b++)
#pragma unroll
            for (int c = 0; c < 4; c++) acc[a][b][c] = 0.f;

    uint32_t sbase0 = smem_u32(sm);
    int nch = K >> 6;

    auto issue = [&](int c) {
        uint32_t sb = sbase0 + (uint32_t)(c & 1) * STG;
        int k0 = c * 64;
#pragma unroll
        for (int i = 0; i < 4; ++i) {
            int q = tid + i * 256;
            int r = q >> 3, c16 = q & 7;
            CP_ASYNC16(sb + (uint32_t)(r * PADK + c16 * 8) * 2,
                       gA + (size_t)r * K + k0 + c16 * 8);
        }
#pragma unroll
        for (int i = 0; i < NT / 32; ++i) {
            int q = tid + i * 256;
            int r = q >> 3, c16 = q & 7;
            CP_ASYNC16(sb + (uint32_t)(ATILE_E + r * PADK + c16 * 8) * 2,
                       gBh + (size_t)r * K + k0 + c16 * 8);
        }
#pragma unroll
        for (int i = 0; i < NT / 32; ++i) {
            int q = tid + i * 256;
            int r = q >> 3, c16 = q & 7;
            CP_ASYNC16(sb + (uint32_t)(ATILE_E + BTILE_E + r * PADK + c16 * 8) * 2,
                       gBl + (size_t)r * K + k0 + c16 * 8);
        }
        CP_COMMIT();
    };

    issue(0);
    for (int c = 0; c < nch; ++c) {
        if (c + 1 < nch) {
            issue(c + 1);
            asm volatile("cp.async.wait_group 1;" ::: "memory");
        } else {
            asm volatile("cp.async.wait_group 0;" ::: "memory");
        }
        __syncthreads();
        uint32_t sb = sbase0 + (uint32_t)(c & 1) * STG;
        uint32_t sA = sb;
        uint32_t sBh = sb + ATILE_E * 2, sBl = sb + (ATILE_E + BTILE_E) * 2;
        int arow = lane & 15, acg = lane >> 4;
#pragma unroll
        for (int kh = 0; kh < 4; ++kh) {
            int kb = kh * 16;
            uint32_t af[TMW][4], bfh[2][4], bfl[2][4];
#pragma unroll
            for (int tm = 0; tm < TMW; ++tm) {
                uint32_t off = (uint32_t)((wm * (TMW * 16) + tm * 16 + arow) * PADK + kb + acg * 8) * 2;
                ldmx4(af[tm], sA + off);
            }
#pragma unroll
            for (int t2 = 0; t2 < 2; ++t2) {
                uint32_t off = (uint32_t)((wn * 32 + t2 * 16 + arow) * PADK + kb + acg * 8) * 2;
                ldmx4(bfh[t2], sBh + off);
                ldmx4(bfl[t2], sBl + off);
            }
#pragma unroll
            for (int tm = 0; tm < TMW; ++tm)
#pragma unroll
                for (int tn = 0; tn < 4; ++tn) {
                    int t2 = tn >> 1, sel = tn & 1;
                    mma_hf(acc[tm][tn], af[tm], bfh[t2][sel], bfh[t2][sel + 2]);
                    mma_hf(acc[tm][tn], af[tm], bfl[t2][sel], bfl[t2][sel + 2]);
                }
        }
        __syncthreads();
    }

    int mrow = lane >> 2, ncol = (lane & 3) * 2;
#pragma unroll
    for (int tm = 0; tm < TMW; ++tm) {
#pragma unroll
        for (int tn = 0; tn < 4; ++tn) {
            int n = n0 + wn * 32 + tn * 8 + ncol;
            float2 bs = *(const float2*)&bias[n];
#pragma unroll
            for (int half = 0; half < 2; ++half) {
                int mm = m0 + wm * (TMW * 16) + tm * 16 + mrow + half * 8;
                float v0 = acc[tm][tn][half * 2 + 0] + bs.x;
                float v1 = acc[tm][tn][half * 2 + 1] + bs.y;
                size_t o = (size_t)mm * ldC + n;
                if (ep == 0 || ep == 3) {
                    if (ep == 0 || n < DD)          // ep3: only Q third read later
                        *(float2*)&C[o] = make_float2(v0, v1);
                    if (ep == 3) {
                        int bq = mm >> 10, iq = mm & 1023;
                        int hq = (n >> 6) & 3, dq = n & 63;
                        size_t qo = ((size_t)(bq * 4 + hq) << 16) + iq * 64 + dq;
                        float h0, h1, l0, l1;
                        if (n < DD) {
                            float q0 = v0 + pvb[n], q1 = v1 + pvb[n + 1];
                            l0 = bflo(q0, &h0); l1 = bflo(q1, &h1);
                            st_bf2(&Qh[qo], h0, h1);
                            st_bf2(&Ql[qo], l0, l1);
                        } else if (n < 2 * DD) {
                            l0 = bflo(v0, &h0); l1 = bflo(v1, &h1);
                            st_bf2(&Kh[qo], h0, h1);
                            st_bf2(&Kl[qo], l0, l1);
                        } else {
                            l0 = bflo(v0, &h0); l1 = bflo(v1, &h1);
                            st_bf2(&Vh[qo], h0, h1);
                            st_bf2(&Vl[qo], l0, l1);
                        }
                    }
                } else if (ep == 1) {
                    v0 = v0 / (1.f + expf(1.f - v0));
                    v1 = v1 / (1.f + expf(1.f - v1));
                    st_hf2(&Oa[o], v0, v1);
                } else {
                    float2 rs = *(const float2*)&resid[o];
                    v0 += rs.x; v1 += rs.y;
                    *(float2*)&C[o] = make_float2(v0, v1);
                    if (Oa) st_hf2(&Oa[o], v0, v1);
                }
            }
        }
    }
}

#define SMEM_MMA2 (2*((128*PADK)+2*(128*PADK))*2)   // 110592
#define SMEM_MMA4 (2*((128*PADK)+2*(64*PADK))*2)    // 73728

// ===================== bd_gemm: shifted rel-pos GEMM (bf16x3) =============
#define BD_SMEM (4*128*80*2)   // 81920
__global__ __launch_bounds__(256, 2) void bd_gemm(
    const __nv_bfloat16* __restrict__ qvh, const __nv_bfloat16* __restrict__ qvl,
    const __nv_bfloat16* __restrict__ ph,  const __nv_bfloat16* __restrict__ pl,
    __half* __restrict__ bd)
{
    int mt = blockIdx.x, it = blockIdx.y, bh = blockIdx.z;
    int i0 = it * 128, m0 = mt * 128;
    if (i0 + m0 + 254 < TT - 1) return;
    int h = bh & 3;

    extern __shared__ __nv_bfloat16 bsm[];
    __nv_bfloat16* Ah = bsm;
    __nv_bfloat16* Al = Ah + 128*80;
    __nv_bfloat16* Bh = Al + 128*80;
    __nv_bfloat16* Bl = Bh + 128*80;
    int tid = threadIdx.x, lane = tid & 31, w = tid >> 5;
    int wm = w & 1, wn = w >> 1;

    const __nv_bfloat16* srcA_h = qvh + ((size_t)bh << 16) + i0 * 64;
    const __nv_bfloat16* srcA_l = qvl + ((size_t)bh << 16) + i0 * 64;
    const __nv_bfloat16* srcB_h = ph  + ((size_t)h  << 16) + m0 * 64;
    const __nv_bfloat16* srcB_l = pl  + ((size_t)h  << 16) + m0 * 64;
#pragma unroll
    for (int i = 0; i < 4; ++i) {
        int idx = tid + i * 256;
        int r = idx >> 3, c8 = idx & 7;
        *(uint4*)&Ah[r*80 + c8*8] = *(const uint4*)&srcA_h[r*64 + c8*8];
        *(uint4*)&Al[r*80 + c8*8] = *(const uint4*)&srcA_l[r*64 + c8*8];
        *(uint4*)&Bh[r*80 + c8*8] = *(const uint4*)&srcB_h[r*64 + c8*8];
        *(uint4*)&Bl[r*80 + c8*8] = *(const uint4*)&srcB_l[r*64 + c8*8];
    }
    __syncthreads();

    uint32_t sAh = smem_u32(Ah), sAl = smem_u32(Al);
    uint32_t sBh = smem_u32(Bh), sBl = smem_u32(Bl);
    float acc[4][4][4];
#pragma unroll
    for (int a = 0; a < 4; a++)
#pragma unroll
        for (int b = 0; b < 4; b++)
#pragma unroll
            for (int c = 0; c < 4; c++) acc[a][b][c] = 0.f;

    int arow = lane & 15, acg = lane >> 4;
#pragma unroll
    for (int kf = 0; kf < 4; ++kf) {
        int kb = kf * 16;
        uint32_t afh[4][4], afl[4][4], bfh[2][4], bfl[2][4];
#pragma unroll
        for (int tm = 0; tm < 4; ++tm) {
            uint32_t off = (uint32_t)((wm * 64 + tm * 16 + arow) * 80 + kb + acg * 8) * 2;
            ldmx4(afh[tm], sAh + off);
            ldmx4(afl[tm], sAl + off);
        }
#pragma unroll
        for (int t2 = 0; t2 < 2; ++t2) {
            uint32_t off = (uint32_t)((wn * 32 + t2 * 16 + arow) * 80 + kb + acg * 8) * 2;
            ldmx4(bfh[t2], sBh + off);
            ldmx4(bfl[t2], sBl + off);
        }
#pragma unroll
        for (int tm = 0; tm < 4; ++tm)
#pragma unroll
            for (int tn = 0; tn < 4; ++tn) {
                int t2 = tn >> 1, sel = tn & 1;
                uint32_t b0 = bfh[t2][sel], b1 = bfh[t2][sel + 2];
                uint32_t l0 = bfl[t2][sel], l1 = bfl[t2][sel + 2];
                mma_bf(acc[tm][tn], afh[tm], b0, b1);
                mma_bf(acc[tm][tn], afl[tm], b0, b1);
                mma_bf(acc[tm][tn], afh[tm], l0, l1);
            }
    }

    int mrow = lane >> 2, ncol = (lane & 3) * 2;
#pragma unroll
    for (int tm = 0; tm < 4; ++tm)
#pragma unroll
        for (int tn = 0; tn < 4; ++tn)
#pragma unroll
            for (int half = 0; half < 2; ++half) {
                int i = i0 + wm * 64 + tm * 16 + mrow + half * 8;
                int m = m0 + wn * 32 + tn * 8 + ncol;
#pragma unroll
                for (int e = 0; e < 2; ++e) {
                    int j = m + e + i - (TT - 1);
                    if (j >= 0 && j <= i)
                        bd[((size_t)bh << 20) + ((size_t)i << 10) + j] =
                            __float2half_rn(acc[tm][tn][half * 2 + e]);
                }
            }
}

// ===================== fused flash attention (bf16x3) =====================
#define FL_SMEM (2*128*80*2 + 2*64*136*2)   // 75776
__global__ __launch_bounds__(256, 1) void flash_kernel(
    const float* __restrict__ qkv,
    const __nv_bfloat16* __restrict__ KhG, const __nv_bfloat16* __restrict__ KlG,
    const __nv_bfloat16* __restrict__ VhG, const __nv_bfloat16* __restrict__ VlG,
    const __half* __restrict__ bd,
    const float* __restrict__ ub_all, const int* __restrict__ lens,
    __half* __restrict__ Ta)
{
    extern __shared__ __nv_bfloat16 fsm[];
    __nv_bfloat16* Kh = fsm;
    __nv_bfloat16* Kl = Kh + 128*80;
    __nv_bfloat16* Vh = Kl + 128*80;
    __nv_bfloat16* Vl = Vh + 64*136;
    uint32_t sKh = smem_u32(Kh), sKl = smem_u32(Kl);
    uint32_t sVh = smem_u32(Vh), sVl = smem_u32(Vl);

    int tid = threadIdx.x, lane = tid & 31, w = tid >> 5;
    int bh = blockIdx.y, b = bh >> 2, h = bh & 3;
    int i0 = ((int)gridDim.x - 1 - (int)blockIdx.x) * 128;
    int len = lens[b];
    int arow = lane & 15, acg = lane >> 4;
    int r_q = lane >> 2, cq = (lane & 3) * 2;
    size_t kvbase = ((size_t)bh << 16);

    {
        int d4 = (tid & 15) * 4, r0 = tid >> 4;
        float4 uu = *(const float4*)&ub_all[h * DKK + d4];
#pragma unroll
        for (int it = 0; it < 8; ++it) {
            int r = r0 + it * 16;
            float4 v = *(const float4*)&qkv[((size_t)(b * TT + i0 + r)) * 768 + h * 64 + d4];
            float vv[4] = {v.x + uu.x, v.y + uu.y, v.z + uu.z, v.w + uu.w};
#pragma unroll
            for (int q = 0; q < 4; ++q) {
                float hi; float lo = bflo(vv[q], &hi);
                Kh[r * 80 + d4 + q] = __float2bfloat16(hi);
                Kl[r * 80 + d4 + q] = __float2bfloat16(lo);
            }
        }
    }
    __syncthreads();
    uint32_t quh[4][4], qul[4][4];
#pragma unroll
    for (int kf = 0; kf < 4; ++kf) {
        uint32_t off = (uint32_t)((w * 16 + arow) * 80 + kf * 16 + acg * 8) * 2;
        ldmx4(quh[kf], sKh + off);
        ldmx4(qul[kf], sKl + off);
    }

    float Of[8][4];
#pragma unroll
    for (int nf = 0; nf < 8; ++nf)
#pragma unroll
        for (int e = 0; e < 4; ++e) Of[nf][e] = 0.f;
    float mrun[2] = {-1e30f, -1e30f}, lrun[2] = {0.f, 0.f};

    for (int j0 = 0; j0 <= i0; j0 += 128) {
        __syncthreads();
#pragma unroll
        for (int i2 = 0; i2 < 4; ++i2) {
            int idx = tid + i2 * 256;
            int r = idx >> 3, c8 = idx & 7;
            uint32_t so = (uint32_t)(r * 80 + c8 * 8) * 2;
            CP_ASYNC16(sKh + so, &KhG[kvbase + (size_t)(j0 + r) * 64 + c8 * 8]);
            CP_ASYNC16(sKl + so, &KlG[kvbase + (size_t)(j0 + r) * 64 + c8 * 8]);
        }
        CP_COMMIT();
        {
            int jj0 = tid & 15, dq = (tid >> 4) * 4;
#pragma unroll
            for (int it = 0; it < 8; ++it) {
                int j = jj0 + it * 16;
                uint2 rh = *(const uint2*)&VhG[kvbase + (size_t)(j0 + j) * 64 + dq];
                uint2 rl = *(const uint2*)&VlG[kvbase + (size_t)(j0 + j) * 64 + dq];
                __nv_bfloat162 h01 = *(__nv_bfloat162*)&rh.x;
                __nv_bfloat162 h23 = *(__nv_bfloat162*)&rh.y;
                __nv_bfloat162 l01 = *(__nv_bfloat162*)&rl.x;
                __nv_bfloat162 l23 = *(__nv_bfloat162*)&rl.y;
                Vh[(dq + 0) * 136 + j] = h01.x;
                Vh[(dq + 1) * 136 + j] = h01.y;
                Vh[(dq + 2) * 136 + j] = h23.x;
                Vh[(dq + 3) * 136 + j] = h23.y;
                Vl[(dq + 0) * 136 + j] = l01.x;
                Vl[(dq + 1) * 136 + j] = l01.y;
                Vl[(dq + 2) * 136 + j] = l23.x;
                Vl[(dq + 3) * 136 + j] = l23.y;
            }
        }
        asm volatile("cp.async.wait_group 0;" ::: "memory");
        __syncthreads();

        float S[16][4];
#pragma unroll
        for (int tn = 0; tn < 16; ++tn)
#pragma unroll
            for (int e = 0; e < 4; ++e) S[tn][e] = 0.f;
#pragma unroll
        for (int t2 = 0; t2 < 8; ++t2) {
#pragma unroll
            for (int kf = 0; kf < 4; ++kf) {
                uint32_t bh4[4], bl4[4];
                uint32_t off = (uint32_t)((t2 * 16 + arow) * 80 + kf * 16 + acg * 8) * 2;
                ldmx4(bh4, sKh + off);
                ldmx4(bl4, sKl + off);
#pragma unroll
                for (int sel = 0; sel < 2; ++sel) {
                    int tn = t2 * 2 + sel;
                    mma_bf(S[tn], quh[kf], bh4[sel], bh4[sel + 2]);
                    mma_bf(S[tn], qul[kf], bh4[sel], bh4[sel + 2]);
                    mma_bf(S[tn], quh[kf], bl4[sel], bl4[sel + 2]);
                }
            }
        }

        float mx[2] = {-1e30f, -1e30f};
#pragma unroll
        for (int tn = 0; tn < 16; ++tn) {
            int jc = j0 + tn * 8 + cq;
#pragma unroll
            for (int half = 0; half < 2; ++half) {
                int i = i0 + w * 16 + r_q + 8 * half;
                __half2 bh2 = *(const __half2*)&bd[((size_t)bh << 20) + ((size_t)i << 10) + jc];
                float2 bv = __half22float2(bh2);
                float v0 = (jc > i || jc >= len) ? -1e30f : (S[tn][half*2+0] + bv.x) * SCALE;
                float v1 = (jc + 1 > i || jc + 1 >= len) ? -1e30f : (S[tn][half*2+1] + bv.y) * SCALE;
                S[tn][half*2+0] = v0; S[tn][half*2+1] = v1;
                mx[half] = fmaxf(mx[half], fmaxf(v0, v1));
            }
        }
#pragma unroll
        for (int s = 1; s <= 2; s <<= 1) {
            mx[0] = fmaxf(mx[0], __shfl_xor_sync(0xFFFFFFFFu, mx[0], s));
            mx[1] = fmaxf(mx[1], __shfl_xor_sync(0xFFFFFFFFu, mx[1], s));
        }
        float newm[2], corr[2], rsum[2] = {0.f, 0.f};
#pragma unroll
        for (int half = 0; half < 2; ++half) {
            newm[half] = fmaxf(mrun[half], mx[half]);
            corr[half] = __expf(mrun[half] - newm[half]);
        }
#pragma unroll
        for (int tn = 0; tn < 16; ++tn)
#pragma unroll
            for (int half = 0; half < 2; ++half) {
                float p0 = __expf(S[tn][half*2+0] - newm[half]);
                float p1 = __expf(S[tn][half*2+1] - newm[half]);
                S[tn][half*2+0] = p0; S[tn][half*2+1] = p1;
                rsum[half] += p0 + p1;
            }
#pragma unroll
        for (int s = 1; s <= 2; s <<= 1) {
            rsum[0] += __shfl_xor_sync(0xFFFFFFFFu, rsum[0], s);
            rsum[1] += __shfl_xor_sync(0xFFFFFFFFu, rsum[1], s);
        }
#pragma unroll
        for (int half = 0; half < 2; ++half) {
            lrun[half] = lrun[half] * corr[half] + rsum[half];
            mrun[half] = newm[half];
        }
#pragma unroll
        for (int nf = 0; nf < 8; ++nf) {
            Of[nf][0] *= corr[0]; Of[nf][1] *= corr[0];
            Of[nf][2] *= corr[1]; Of[nf][3] *= corr[1];
        }
        uint32_t pfh[8][4], pfl[8][4];
#pragma unroll
        for (int kf = 0; kf < 8; ++kf) {
            float h0, h1, l0, l1;
            l0 = bflo(S[2*kf][0], &h0);  l1 = bflo(S[2*kf][1], &h1);
            pfh[kf][0] = packbf2(h0, h1); pfl[kf][0] = packbf2(l0, l1);
            l0 = bflo(S[2*kf][2], &h0);  l1 = bflo(S[2*kf][3], &h1);
            pfh[kf][1] = packbf2(h0, h1); pfl[kf][1] = packbf2(l0, l1);
            l0 = bflo(S[2*kf+1][0], &h0); l1 = bflo(S[2*kf+1][1], &h1);
            pfh[kf][2] = packbf2(h0, h1); pfl[kf][2] = packbf2(l0, l1);
            l0 = bflo(S[2*kf+1][2], &h0); l1 = bflo(S[2*kf+1][3], &h1);
            pfh[kf][3] = packbf2(h0, h1); pfl[kf][3] = packbf2(l0, l1);
        }
#pragma unroll
        for (int nf2 = 0; nf2 < 4; ++nf2) {
#pragma unroll
            for (int kf = 0; kf < 8; ++kf) {
                uint32_t vh4[4], vl4[4];
                uint32_t off = (uint32_t)((nf2 * 16 + arow) * 136 + kf * 16 + acg * 8) * 2;
                ldmx4(vh4, sVh + off);
                ldmx4(vl4, sVl + off);
#pragma unroll
                for (int sel = 0; sel < 2; ++sel) {
                    int nf = nf2 * 2 + sel;
                    mma_bf(Of[nf], pfh[kf], vh4[sel], vh4[sel + 2]);
                    mma_bf(Of[nf], pfl[kf], vh4[sel], vh4[sel + 2]);
                    mma_bf(Of[nf], pfh[kf], vl4[sel], vl4[sel + 2]);
                }
            }
        }
    }

    float inv[2] = {1.f / lrun[0], 1.f / lrun[1]};
#pragma unroll
    for (int nf = 0; nf < 8; ++nf)
#pragma unroll
        for (int half = 0; half < 2; ++half) {
            int i = i0 + w * 16 + r_q + 8 * half;
            int d = h * 64 + nf * 8 + cq;
            size_t o = (size_t)(b * TT + i) * DD + d;
            st_hf2(&Ta[o], Of[nf][half*2+0] * inv[half], Of[nf][half*2+1] * inv[half]);
        }
}

// ---------------- fp32 -> fp16 hi/lo weight split --------------------------
__global__ void splitw_kernel(const float* __restrict__ s, __half* __restrict__ h,
                              __half* __restrict__ l, int n)
{
    int idx = 4 * (blockIdx.x * 256 + threadIdx.x);
    if (idx >= n) return;
    float4 v = *(const float4*)&s[idx];
    float vv[4] = {v.x, v.y, v.z, v.w};
#pragma unroll
    for (int q = 0; q < 4; ++q) {
        __half hi = __float2half_rn(vv[q]);
        h[idx+q] = hi;
        l[idx+q] = __float2half_rn(vv[q] - __half2float(hi));
    }
}

// ---------------- SIMT GEMM (embed + batched p) ----------------------------
#define BM 128
#define BN 128
#define BKK 16
__global__ __launch_bounds__(256) void gemm_kernel(
    const float* __restrict__ A, const float* __restrict__ W,
    const float* __restrict__ bias, float* __restrict__ C,
    __nv_bfloat16* __restrict__ Ph, __nv_bfloat16* __restrict__ Pl,
    int M, int N, int K)
{
    __shared__ float As[BKK][BM];
    __shared__ float Ws[BKK][BN];
    int tid = threadIdx.x;
    int tx = tid & 15, ty = tid >> 4;
    int m0 = blockIdx.y * BM, n0 = blockIdx.x * BN;
    int z = blockIdx.z;
    const float* Wz = W + (size_t)z * DD * DD;
    float acc[8][8];
#pragma unroll
    for (int e = 0; e < 8; e++)
#pragma unroll
        for (int f = 0; f < 8; f++) acc[e][f] = 0.f;
    for (int k0 = 0; k0 < K; k0 += BKK) {
#pragma unroll
        for (int i = 0; i < 8; i++) {
            int q = tid + i * 256;
            int r = q >> 4, kk = q & 15;
            As[kk][r] = A[(m0 + r) * K + k0 + kk];
            Ws[kk][r] = Wz[(n0 + r) * K + k0 + kk];
        }
        __syncthreads();
#pragma unroll
        for (int kk = 0; kk < BKK; kk++) {
            float a[8], wv[8];
#pragma unroll
            for (int e = 0; e < 8; e++) a[e] = As[kk][ty * 8 + e];
#pragma unroll
            for (int f = 0; f < 8; f++) wv[f] = Ws[kk][tx * 8 + f];
#pragma unroll
            for (int e = 0; e < 8; e++)
#pragma unroll
                for (int f = 0; f < 8; f++) acc[e][f] += a[e] * wv[f];
        }
        __syncthreads();
    }
#pragma unroll
    for (int e = 0; e < 8; e++) {
        int m = m0 + ty * 8 + e;
#pragma unroll
        for (int f = 0; f < 8; f++) {
            int n = n0 + tx * 8 + f;
            float v = acc[e][f];
            if (bias) v += bias[n];
            if (Ph) {
                int hq = n >> 6, dq = n & 63;
                size_t o = ((size_t)(z * HH + hq) << 16) + m * 64 + dq;
                float hi; float lo = bflo(v, &hi);
                Ph[o] = __float2bfloat16(hi);
                Pl[o] = __float2bfloat16(lo);
            } else {
                C[m * N + n] = v;
            }
        }
    }
}

// ---------------- BasicNorm (warp per row) + fp16 out ---------------------
__global__ __launch_bounds__(256) void norm_kernel(
    float* __restrict__ x, __half* __restrict__ xa)
{
    int row = blockIdx.x * 8 + (threadIdx.x >> 5);
    int lane = threadIdx.x & 31;
    float* p = x + (size_t)row * DD;
    float4 a = *(float4*)&p[lane * 8];
    float4 b = *(float4*)&p[lane * 8 + 4];
    float s = a.x*a.x + a.y*a.y + a.z*a.z + a.w*a.w
            + b.x*b.x + b.y*b.y + b.z*b.z + b.w*b.w;
#pragma unroll
    for (int o = 16; o > 0; o >>= 1) s += __shfl_xor_sync(0xFFFFFFFFu, s, o);
    float sc = rsqrtf(s * (1.f / DD) + EPSN);
    float vv[8] = {a.x*sc, a.y*sc, a.z*sc, a.w*sc, b.x*sc, b.y*sc, b.z*sc, b.w*sc};
    *(float4*)&p[lane * 8]     = make_float4(vv[0], vv[1], vv[2], vv[3]);
    *(float4*)&p[lane * 8 + 4] = make_float4(vv[4], vv[5], vv[6], vv[7]);
    size_t o = (size_t)row * DD + lane * 8;
#pragma unroll
    for (int q = 0; q < 8; q += 2) st_hf2(&xa[o + q], vv[q], vv[q+1]);
}

// ---------------- rel positional embedding --------------------------------
__global__ void pe_kernel(float* __restrict__ pe)
{
    int m = blockIdx.x;
    int c = threadIdx.x;
    int pos = (TT - 1) - m;
    int j = c >> 1;
    float div = expf((2.f * j) * (-9.210340371976184f / (float)DD));
    float ang = (float)pos * div;
    pe[m * DD + c] = (c & 1) ? cosf(ang) : sinf(ang);
}

// ---------------- output copy ---------------------------------------------
__global__ void output_kernel(const float* __restrict__ x,
                              const int* __restrict__ lens,
                              float* __restrict__ out, int out_size)
{
    int idx = blockIdx.x * 256 + threadIdx.x;
    if (idx >= out_size) return;
    if (idx < ROWS * DD) out[idx] = x[idx];
    else {
        int t = idx - ROWS * DD;
        out[idx] = (t < BB) ? (float)lens[t] : 0.f;
    }
}

// ============================ host driver =================================
extern "C" void kernel_launch(void* const* d_in, const int* in_sizes, int n_in,
                              void* d_out, int out_size)
{
    const float* x_in      = (const float*)d_in[0];
    const int*   lens      = (const int*)  d_in[1];
    const float* embed_W   = (const float*)d_in[2];
    const float* embed_b   = (const float*)d_in[3];
    const float* in_proj_W = (const float*)d_in[4];
    const float* in_proj_b = (const float*)d_in[5];
    const float* pos_W     = (const float*)d_in[6];
    const float* pos_u     = (const float*)d_in[7];
    const float* pos_v     = (const float*)d_in[8];
    const float* out_W     = (const float*)d_in[9];
    const float* out_b     = (const float*)d_in[10];
    const float* ff1_W     = (const float*)d_in[11];
    const float* ff1_b     = (const float*)d_in[12];
    const float* ff2_W     = (const float*)d_in[13];
    const float* ff2_b     = (const float*)d_in[14];

    float *gx, *gqkv, *gpe;
    __half *gbd;
    cudaGetSymbolAddress((void**)&gx,   g_x);
    cudaGetSymbolAddress((void**)&gqkv, g_qkv);
    cudaGetSymbolAddress((void**)&gpe,  g_pe);
    cudaGetSymbolAddress((void**)&gbd,  g_bd);
    __half *xa,*ta,*ha,*wqh,*wql,*woh,*wol,*w1h,*w1l,*w2h,*w2l;
    __nv_bfloat16 *qvh,*qvl,*kh,*kl,*vh,*vl,*ph,*pl;
    cudaGetSymbolAddress((void**)&xa, g_xa);
    cudaGetSymbolAddress((void**)&ta, g_ta);
    cudaGetSymbolAddress((void**)&ha, g_ha);
    cudaGetSymbolAddress((void**)&wqh, g_wqkvh); cudaGetSymbolAddress((void**)&wql, g_wqkvl);
    cudaGetSymbolAddress((void**)&woh, g_wouth); cudaGetSymbolAddress((void**)&wol, g_woutl);
    cudaGetSymbolAddress((void**)&w1h, g_wf1h);  cudaGetSymbolAddress((void**)&w1l, g_wf1l);
    cudaGetSymbolAddress((void**)&w2h, g_wf2h);  cudaGetSymbolAddress((void**)&w2l, g_wf2l);
    cudaGetSymbolAddress((void**)&qvh, g_qvh);   cudaGetSymbolAddress((void**)&qvl, g_qvl);
    cudaGetSymbolAddress((void**)&kh,  g_kh);    cudaGetSymbolAddress((void**)&kl,  g_kl);
    cudaGetSymbolAddress((void**)&vh,  g_vh);    cudaGetSymbolAddress((void**)&vl,  g_vl);
    cudaGetSymbolAddress((void**)&ph,  g_ph);    cudaGetSymbolAddress((void**)&pl,  g_pl);

    cudaFuncSetAttribute(mma_gemm<2>,  cudaFuncAttributeMaxDynamicSharedMemorySize, SMEM_MMA2);
    cudaFuncSetAttribute(mma_gemm<4>,  cudaFuncAttributeMaxDynamicSharedMemorySize, SMEM_MMA4);
    cudaFuncSetAttribute(bd_gemm,      cudaFuncAttributeMaxDynamicSharedMemorySize, BD_SMEM);
    cudaFuncSetAttribute(flash_kernel, cudaFuncAttributeMaxDynamicSharedMemorySize, FL_SMEM);

    // ---- launch order keeps 0-based index 3 == mma_gemm<2> (qkv layer 0)
    splitw_kernel<<<(NL*3*DD*DD)/1024, 256>>>(in_proj_W, wqh, wql, NL*3*DD*DD);
    gemm_kernel<<<dim3(DD/BN, ROWS/BM), 256>>>(x_in, embed_W, embed_b, gx,
                                               nullptr, nullptr, ROWS, DD, DI);
    norm_kernel<<<ROWS/8, 256>>>(gx, xa);
    // 3: qkv layer 0  <-- ncu capture lands here
    mma_gemm<2><<<dim3(3*DD/128, ROWS/128), 256, SMEM_MMA2>>>(
        xa, wqh, wql, in_proj_b, nullptr, gqkv, nullptr,
        pos_v, qvh, qvl, kh, kl, vh, vl, DD, 3*DD, 3);
    pe_kernel<<<TT, DD>>>(gpe);
    // batched p for ALL layers
    gemm_kernel<<<dim3(DD/BN, TT/BM, NL), 256>>>(
        gpe, pos_W, nullptr, nullptr, ph, pl, TT, DD, DD);
    splitw_kernel<<<(NL*DD*DD)/1024,   256>>>(out_W, woh, wol, NL*DD*DD);
    splitw_kernel<<<(NL*FFD*DD)/1024,  256>>>(ff1_W, w1h, w1l, NL*FFD*DD);
    splitw_kernel<<<(NL*DD*FFD)/1024,  256>>>(ff2_W, w2h, w2l, NL*DD*FFD);

    for (int l = 0; l < NL; l++) {
        if (l > 0) {
            mma_gemm<2><<<dim3(3*DD/128, ROWS/128), 256, SMEM_MMA2>>>(
                xa, wqh + (size_t)l*3*DD*DD, wql + (size_t)l*3*DD*DD,
                in_proj_b + l*3*DD, nullptr, gqkv, nullptr,
                pos_v + l*HH*DKK, qvh, qvl, kh, kl, vh, vl, DD, 3*DD, 3);
        }
        bd_gemm<<<dim3(TT/128, TT/128, BB*HH), 256, BD_SMEM>>>(
            qvh, qvl, ph + (size_t)l*HH*TT*DKK, pl + (size_t)l*HH*TT*DKK, gbd);
        flash_kernel<<<dim3(TT/128, BB*HH), 256, FL_SMEM>>>(
            gqkv, kh, kl, vh, vl, gbd, pos_u + l*HH*DKK, lens, ta);
        // out projection + residual -> x (+ xa fp16 for ff1)  [128x64 tiles]
        mma_gemm<4><<<dim3(DD/64, ROWS/128), 256, SMEM_MMA4>>>(
            ta, woh + (size_t)l*DD*DD, wol + (size_t)l*DD*DD,
            out_b + l*DD, gx, gx, xa,
            nullptr, nullptr, nullptr, nullptr, nullptr, nullptr, nullptr, DD, DD, 2);
        // FF1 + double_swish -> ha (fp16)
        mma_gemm<2><<<dim3(FFD/128, ROWS/128), 256, SMEM_MMA2>>>(
            xa, w1h + (size_t)l*FFD*DD, w1l + (size_t)l*FFD*DD,
            ff1_b + l*FFD, nullptr, nullptr, ha,
            nullptr, nullptr, nullptr, nullptr, nullptr, nullptr, nullptr, DD, FFD, 1);
        // FF2 + residual -> x  [128x64 tiles]
        mma_gemm<4><<<dim3(DD/64, ROWS/128), 256, SMEM_MMA4>>>(
            ha, w2h + (size_t)l*DD*FFD, w2l + (size_t)l*DD*FFD,
            ff2_b + l*DD, gx, gx, nullptr,
            nullptr, nullptr, nullptr, nullptr, nullptr, nullptr, nullptr, FFD, DD, 2);
        norm_kernel<<<ROWS/8, 256>>>(gx, xa);
    }

    output_kernel<<<(out_size + 255) / 256, 256>>>(gx, lens, (float*)d_out, out_size);
}

// round 15
// speedup vs baseline: 1.1918x; 1.1918x over previous
#include <cuda_runtime.h>
#include <cuda_bf16.h>
#include <cuda_fp16.h>
#include <math.h>
#include <stdint.h>

// Problem constants
#define BB 8
#define TT 1024
#define DI 80
#define DD 256
#define HH 4
#define DKK 64
#define FFD 2048
#define NL 6
#define ROWS (BB*TT)        // 8192
#define SCALE 0.125f
#define EPSN 0.25f

// -------- scratch (static device globals) ----------
__device__ float g_x[ROWS*DD];
__device__ float g_qkv[ROWS*3*DD];      // only Q third written/read
__device__ float g_pe[TT*DD];
__device__ __half g_bd[BB*HH*TT*TT];    // pre-shifted rel-pos term (fp16)

// fp16 activation buffers
__device__ __half g_xa[ROWS*DD];
__device__ __half g_ta[ROWS*DD];
__device__ __half g_ha[ROWS*FFD];
// fp16 weights (single precision fp16 now)
__device__ __half g_wqkv[NL*3*DD*DD];
__device__ __half g_wout[NL*DD*DD];
__device__ __half g_wf1[NL*FFD*DD];
__device__ __half g_wf2[NL*DD*FFD];
// bf16 splits for attention-score path
__device__ __nv_bfloat16 g_qvh[BB*HH*TT*DKK], g_qvl[BB*HH*TT*DKK];
__device__ __nv_bfloat16 g_kh[BB*HH*TT*DKK],  g_kl[BB*HH*TT*DKK];
__device__ __nv_bfloat16 g_vh[BB*HH*TT*DKK],  g_vl[BB*HH*TT*DKK];
__device__ __nv_bfloat16 g_ph[NL*HH*TT*DKK], g_pl[NL*HH*TT*DKK];

// ===================== PTX helpers (arch-neutral, sm_80+) =================
__device__ __forceinline__ uint32_t smem_u32(const void* p) {
    uint32_t a;
    asm("{ .reg .u64 t; cvta.to.shared.u64 t, %1; cvt.u32.u64 %0, t; }" : "=r"(a) : "l"(p));
    return a;
}
#define CP_ASYNC16(sa, ga) asm volatile("cp.async.cg.shared.global [%0], [%1], 16;" :: "r"(sa), "l"(ga))
#define CP_COMMIT()        asm volatile("cp.async.commit_group;" ::: "memory")

__device__ __forceinline__ void ldmx4(uint32_t (&r)[4], uint32_t addr) {
    asm volatile("ldmatrix.sync.aligned.m8n8.x4.shared.b16 {%0,%1,%2,%3}, [%4];"
        : "=r"(r[0]), "=r"(r[1]), "=r"(r[2]), "=r"(r[3]) : "r"(addr));
}
__device__ __forceinline__ void mma_bf(float (&c)[4], const uint32_t (&a)[4],
                                       uint32_t b0, uint32_t b1) {
    asm volatile("mma.sync.aligned.m16n8k16.row.col.f32.bf16.bf16.f32 "
        "{%0,%1,%2,%3}, {%4,%5,%6,%7}, {%8,%9}, {%0,%1,%2,%3};"
        : "+f"(c[0]), "+f"(c[1]), "+f"(c[2]), "+f"(c[3])
        : "r"(a[0]), "r"(a[1]), "r"(a[2]), "r"(a[3]), "r"(b0), "r"(b1));
}
__device__ __forceinline__ void mma_hf(float (&c)[4], const uint32_t (&a)[4],
                                       uint32_t b0, uint32_t b1) {
    asm volatile("mma.sync.aligned.m16n8k16.row.col.f32.f16.f16.f32 "
        "{%0,%1,%2,%3}, {%4,%5,%6,%7}, {%8,%9}, {%0,%1,%2,%3};"
        : "+f"(c[0]), "+f"(c[1]), "+f"(c[2]), "+f"(c[3])
        : "r"(a[0]), "r"(a[1]), "r"(a[2]), "r"(a[3]), "r"(b0), "r"(b1));
}
__device__ __forceinline__ uint32_t packbf2(float a, float b) {
    __nv_bfloat162 t = __floats2bfloat162_rn(a, b);
    return *(uint32_t*)&t;
}
__device__ __forceinline__ float bflo(float v, float* hi) {
    __nv_bfloat16 h = __float2bfloat16(v);
    *hi = __bfloat162float(h);
    return v - *hi;
}
__device__ __forceinline__ void st_bf2(__nv_bfloat16* p, float a, float b) {
    __nv_bfloat162 t = __floats2bfloat162_rn(a, b);
    *(__nv_bfloat162*)p = t;
}
__device__ __forceinline__ void st_hf2(__half* p, float a, float b) {
    *(__half2*)p = __floats2half2_rn(a, b);
}

// ===================== fp16 mma.sync GEMM (linear layers) =================
// Plain fp16 A and B, fp32 accum. K-chunk 64, PADK 72.
// WM=2 -> 128x128 tile (2x4 warps); WM=4 -> 128x64 tile (4x2 warps).
#define PADK 72

template<int WM>
__global__ __launch_bounds__(256, 2) void mma_gemm(
    const __half* __restrict__ A, const __half* __restrict__ B,
    const float* __restrict__ bias, const float* __restrict__ resid,
    float* __restrict__ C, __half* __restrict__ Oa,
    const float* __restrict__ pvb,
    __nv_bfloat16* __restrict__ Qh, __nv_bfloat16* __restrict__ Ql,
    __nv_bfloat16* __restrict__ Kh, __nv_bfloat16* __restrict__ Kl,
    __nv_bfloat16* __restrict__ Vh, __nv_bfloat16* __restrict__ Vl,
    int K, int ldC, int ep)
{
    constexpr int NT     = (8 / WM) * 32;
    constexpr int TMW    = 128 / (WM * 16);
    constexpr int ATILE_E = 128 * PADK;
    constexpr int BTILE_E = NT * PADK;
    constexpr int STG    = (ATILE_E + BTILE_E) * 2;

    extern __shared__ __half sm[];
    int tid = threadIdx.x, lane = tid & 31, w = tid >> 5;
    int wm = w % WM, wn = w / WM;
    int m0 = blockIdx.y * 128, n0 = blockIdx.x * NT;
    const __half* gA = A + (size_t)m0 * K;
    const __half* gB = B + (size_t)n0 * K;

    float acc[TMW][4][4];
#pragma unroll
    for (int a = 0; a < TMW; a++)
#pragma unroll
        for (int b = 0; b < 4; b++)
#pragma unroll
            for (int c = 0; c < 4; c++) acc[a][b][c] = 0.f;

    uint32_t sbase0 = smem_u32(sm);
    int nch = K >> 6;

    auto issue = [&](int c) {
        uint32_t sb = sbase0 + (uint32_t)(c & 1) * STG;
        int k0 = c * 64;
#pragma unroll
        for (int i = 0; i < 4; ++i) {          // A: 128 rows x 8 x 16B
            int q = tid + i * 256;
            int r = q >> 3, c16 = q & 7;
            CP_ASYNC16(sb + (uint32_t)(r * PADK + c16 * 8) * 2,
                       gA + (size_t)r * K + k0 + c16 * 8);
        }
#pragma unroll
        for (int i = 0; i < NT / 32; ++i) {    // B: NT rows
            int q = tid + i * 256;
            int r = q >> 3, c16 = q & 7;
            CP_ASYNC16(sb + (uint32_t)(ATILE_E + r * PADK + c16 * 8) * 2,
                       gB + (size_t)r * K + k0 + c16 * 8);
        }
        CP_COMMIT();
    };

    issue(0);
    for (int c = 0; c < nch; ++c) {
        if (c + 1 < nch) {
            issue(c + 1);
            asm volatile("cp.async.wait_group 1;" ::: "memory");
        } else {
            asm volatile("cp.async.wait_group 0;" ::: "memory");
        }
        __syncthreads();
        uint32_t sb = sbase0 + (uint32_t)(c & 1) * STG;
        uint32_t sA = sb, sB = sb + ATILE_E * 2;
        int arow = lane & 15, acg = lane >> 4;
#pragma unroll
        for (int kh = 0; kh < 4; ++kh) {
            int kb = kh * 16;
            uint32_t af[TMW][4], bf[2][4];
#pragma unroll
            for (int tm = 0; tm < TMW; ++tm) {
                uint32_t off = (uint32_t)((wm * (TMW * 16) + tm * 16 + arow) * PADK + kb + acg * 8) * 2;
                ldmx4(af[tm], sA + off);
            }
#pragma unroll
            for (int t2 = 0; t2 < 2; ++t2) {
                uint32_t off = (uint32_t)((wn * 32 + t2 * 16 + arow) * PADK + kb + acg * 8) * 2;
                ldmx4(bf[t2], sB + off);
            }
#pragma unroll
            for (int tm = 0; tm < TMW; ++tm)
#pragma unroll
                for (int tn = 0; tn < 4; ++tn) {
                    int t2 = tn >> 1, sel = tn & 1;
                    mma_hf(acc[tm][tn], af[tm], bf[t2][sel], bf[t2][sel + 2]);
                }
        }
        __syncthreads();
    }

    int mrow = lane >> 2, ncol = (lane & 3) * 2;
#pragma unroll
    for (int tm = 0; tm < TMW; ++tm) {
#pragma unroll
        for (int tn = 0; tn < 4; ++tn) {
            int n = n0 + wn * 32 + tn * 8 + ncol;
            float2 bs = *(const float2*)&bias[n];
#pragma unroll
            for (int half = 0; half < 2; ++half) {
                int mm = m0 + wm * (TMW * 16) + tm * 16 + mrow + half * 8;
                float v0 = acc[tm][tn][half * 2 + 0] + bs.x;
                float v1 = acc[tm][tn][half * 2 + 1] + bs.y;
                size_t o = (size_t)mm * ldC + n;
                if (ep == 0 || ep == 3) {
                    if (ep == 0 || n < DD)
                        *(float2*)&C[o] = make_float2(v0, v1);
                    if (ep == 3) {
                        int bq = mm >> 10, iq = mm & 1023;
                        int hq = (n >> 6) & 3, dq = n & 63;
                        size_t qo = ((size_t)(bq * 4 + hq) << 16) + iq * 64 + dq;
                        float h0, h1, l0, l1;
                        if (n < DD) {
                            float q0 = v0 + pvb[n], q1 = v1 + pvb[n + 1];
                            l0 = bflo(q0, &h0); l1 = bflo(q1, &h1);
                            st_bf2(&Qh[qo], h0, h1);
                            st_bf2(&Ql[qo], l0, l1);
                        } else if (n < 2 * DD) {
                            l0 = bflo(v0, &h0); l1 = bflo(v1, &h1);
                            st_bf2(&Kh[qo], h0, h1);
                            st_bf2(&Kl[qo], l0, l1);
                        } else {
                            l0 = bflo(v0, &h0); l1 = bflo(v1, &h1);
                            st_bf2(&Vh[qo], h0, h1);
                            st_bf2(&Vl[qo], l0, l1);
                        }
                    }
                } else if (ep == 1) {
                    v0 = v0 / (1.f + expf(1.f - v0));
                    v1 = v1 / (1.f + expf(1.f - v1));
                    st_hf2(&Oa[o], v0, v1);
                } else {
                    float2 rs = *(const float2*)&resid[o];
                    v0 += rs.x; v1 += rs.y;
                    *(float2*)&C[o] = make_float2(v0, v1);
                    if (Oa) st_hf2(&Oa[o], v0, v1);
                }
            }
        }
    }
}

#define SMEM_MMA2 (2*((128*PADK)+(128*PADK))*2)   // 73728
#define SMEM_MMA4 (2*((128*PADK)+(64*PADK))*2)    // 55296

// ===================== bd_gemm: shifted rel-pos GEMM (bf16x3) =============
#define BD_SMEM (4*128*80*2)   // 81920
__global__ __launch_bounds__(256, 2) void bd_gemm(
    const __nv_bfloat16* __restrict__ qvh, const __nv_bfloat16* __restrict__ qvl,
    const __nv_bfloat16* __restrict__ ph,  const __nv_bfloat16* __restrict__ pl,
    __half* __restrict__ bd)
{
    int mt = blockIdx.x, it = blockIdx.y, bh = blockIdx.z;
    int i0 = it * 128, m0 = mt * 128;
    if (i0 + m0 + 254 < TT - 1) return;
    int h = bh & 3;

    extern __shared__ __nv_bfloat16 bsm[];
    __nv_bfloat16* Ah = bsm;
    __nv_bfloat16* Al = Ah + 128*80;
    __nv_bfloat16* Bh = Al + 128*80;
    __nv_bfloat16* Bl = Bh + 128*80;
    int tid = threadIdx.x, lane = tid & 31, w = tid >> 5;
    int wm = w & 1, wn = w >> 1;

    const __nv_bfloat16* srcA_h = qvh + ((size_t)bh << 16) + i0 * 64;
    const __nv_bfloat16* srcA_l = qvl + ((size_t)bh << 16) + i0 * 64;
    const __nv_bfloat16* srcB_h = ph  + ((size_t)h  << 16) + m0 * 64;
    const __nv_bfloat16* srcB_l = pl  + ((size_t)h  << 16) + m0 * 64;
#pragma unroll
    for (int i = 0; i < 4; ++i) {
        int idx = tid + i * 256;
        int r = idx >> 3, c8 = idx & 7;
        *(uint4*)&Ah[r*80 + c8*8] = *(const uint4*)&srcA_h[r*64 + c8*8];
        *(uint4*)&Al[r*80 + c8*8] = *(const uint4*)&srcA_l[r*64 + c8*8];
        *(uint4*)&Bh[r*80 + c8*8] = *(const uint4*)&srcB_h[r*64 + c8*8];
        *(uint4*)&Bl[r*80 + c8*8] = *(const uint4*)&srcB_l[r*64 + c8*8];
    }
    __syncthreads();

    uint32_t sAh = smem_u32(Ah), sAl = smem_u32(Al);
    uint32_t sBh = smem_u32(Bh), sBl = smem_u32(Bl);
    float acc[4][4][4];
#pragma unroll
    for (int a = 0; a < 4; a++)
#pragma unroll
        for (int b = 0; b < 4; b++)
#pragma unroll
            for (int c = 0; c < 4; c++) acc[a][b][c] = 0.f;

    int arow = lane & 15, acg = lane >> 4;
#pragma unroll
    for (int kf = 0; kf < 4; ++kf) {
        int kb = kf * 16;
        uint32_t afh[4][4], afl[4][4], bfh[2][4], bfl[2][4];
#pragma unroll
        for (int tm = 0; tm < 4; ++tm) {
            uint32_t off = (uint32_t)((wm * 64 + tm * 16 + arow) * 80 + kb + acg * 8) * 2;
            ldmx4(afh[tm], sAh + off);
            ldmx4(afl[tm], sAl + off);
        }
#pragma unroll
        for (int t2 = 0; t2 < 2; ++t2) {
            uint32_t off = (uint32_t)((wn * 32 + t2 * 16 + arow) * 80 + kb + acg * 8) * 2;
            ldmx4(bfh[t2], sBh + off);
            ldmx4(bfl[t2], sBl + off);
        }
#pragma unroll
        for (int tm = 0; tm < 4; ++tm)
#pragma unroll
            for (int tn = 0; tn < 4; ++tn) {
                int t2 = tn >> 1, sel = tn & 1;
                uint32_t b0 = bfh[t2][sel], b1 = bfh[t2][sel + 2];
                uint32_t l0 = bfl[t2][sel], l1 = bfl[t2][sel + 2];
                mma_bf(acc[tm][tn], afh[tm], b0, b1);
                mma_bf(acc[tm][tn], afl[tm], b0, b1);
                mma_bf(acc[tm][tn], afh[tm], l0, l1);
            }
    }

    int mrow = lane >> 2, ncol = (lane & 3) * 2;
#pragma unroll
    for (int tm = 0; tm < 4; ++tm)
#pragma unroll
        for (int tn = 0; tn < 4; ++tn)
#pragma unroll
            for (int half = 0; half < 2; ++half) {
                int i = i0 + wm * 64 + tm * 16 + mrow + half * 8;
                int m = m0 + wn * 32 + tn * 8 + ncol;
#pragma unroll
                for (int e = 0; e < 2; ++e) {
                    int j = m + e + i - (TT - 1);
                    if (j >= 0 && j <= i)
                        bd[((size_t)bh << 20) + ((size_t)i << 10) + j] =
                            __float2half_rn(acc[tm][tn][half * 2 + e]);
                }
            }
}

// ===================== fused flash attention (bf16x3) =====================
#define FL_SMEM (2*128*80*2 + 2*64*136*2)   // 75776
__global__ __launch_bounds__(256, 1) void flash_kernel(
    const float* __restrict__ qkv,
    const __nv_bfloat16* __restrict__ KhG, const __nv_bfloat16* __restrict__ KlG,
    const __nv_bfloat16* __restrict__ VhG, const __nv_bfloat16* __restrict__ VlG,
    const __half* __restrict__ bd,
    const float* __restrict__ ub_all, const int* __restrict__ lens,
    __half* __restrict__ Ta)
{
    extern __shared__ __nv_bfloat16 fsm[];
    __nv_bfloat16* Kh = fsm;
    __nv_bfloat16* Kl = Kh + 128*80;
    __nv_bfloat16* Vh = Kl + 128*80;
    __nv_bfloat16* Vl = Vh + 64*136;
    uint32_t sKh = smem_u32(Kh), sKl = smem_u32(Kl);
    uint32_t sVh = smem_u32(Vh), sVl = smem_u32(Vl);

    int tid = threadIdx.x, lane = tid & 31, w = tid >> 5;
    int bh = blockIdx.y, b = bh >> 2, h = bh & 3;
    int i0 = ((int)gridDim.x - 1 - (int)blockIdx.x) * 128;
    int len = lens[b];
    int arow = lane & 15, acg = lane >> 4;
    int r_q = lane >> 2, cq = (lane & 3) * 2;
    size_t kvbase = ((size_t)bh << 16);

    {
        int d4 = (tid & 15) * 4, r0 = tid >> 4;
        float4 uu = *(const float4*)&ub_all[h * DKK + d4];
#pragma unroll
        for (int it = 0; it < 8; ++it) {
            int r = r0 + it * 16;
            float4 v = *(const float4*)&qkv[((size_t)(b * TT + i0 + r)) * 768 + h * 64 + d4];
            float vv[4] = {v.x + uu.x, v.y + uu.y, v.z + uu.z, v.w + uu.w};
#pragma unroll
            for (int q = 0; q < 4; ++q) {
                float hi; float lo = bflo(vv[q], &hi);
                Kh[r * 80 + d4 + q] = __float2bfloat16(hi);
                Kl[r * 80 + d4 + q] = __float2bfloat16(lo);
            }
        }
    }
    __syncthreads();
    uint32_t quh[4][4], qul[4][4];
#pragma unroll
    for (int kf = 0; kf < 4; ++kf) {
        uint32_t off = (uint32_t)((w * 16 + arow) * 80 + kf * 16 + acg * 8) * 2;
        ldmx4(quh[kf], sKh + off);
        ldmx4(qul[kf], sKl + off);
    }

    float Of[8][4];
#pragma unroll
    for (int nf = 0; nf < 8; ++nf)
#pragma unroll
        for (int e = 0; e < 4; ++e) Of[nf][e] = 0.f;
    float mrun[2] = {-1e30f, -1e30f}, lrun[2] = {0.f, 0.f};

    for (int j0 = 0; j0 <= i0; j0 += 128) {
        __syncthreads();
#pragma unroll
        for (int i2 = 0; i2 < 4; ++i2) {
            int idx = tid + i2 * 256;
            int r = idx >> 3, c8 = idx & 7;
            uint32_t so = (uint32_t)(r * 80 + c8 * 8) * 2;
            CP_ASYNC16(sKh + so, &KhG[kvbase + (size_t)(j0 + r) * 64 + c8 * 8]);
            CP_ASYNC16(sKl + so, &KlG[kvbase + (size_t)(j0 + r) * 64 + c8 * 8]);
        }
        CP_COMMIT();
        {
            int jj0 = tid & 15, dq = (tid >> 4) * 4;
#pragma unroll
            for (int it = 0; it < 8; ++it) {
                int j = jj0 + it * 16;
                uint2 rh = *(const uint2*)&VhG[kvbase + (size_t)(j0 + j) * 64 + dq];
                uint2 rl = *(const uint2*)&VlG[kvbase + (size_t)(j0 + j) * 64 + dq];
                __nv_bfloat162 h01 = *(__nv_bfloat162*)&rh.x;
                __nv_bfloat162 h23 = *(__nv_bfloat162*)&rh.y;
                __nv_bfloat162 l01 = *(__nv_bfloat162*)&rl.x;
                __nv_bfloat162 l23 = *(__nv_bfloat162*)&rl.y;
                Vh[(dq + 0) * 136 + j] = h01.x;
                Vh[(dq + 1) * 136 + j] = h01.y;
                Vh[(dq + 2) * 136 + j] = h23.x;
                Vh[(dq + 3) * 136 + j] = h23.y;
                Vl[(dq + 0) * 136 + j] = l01.x;
                Vl[(dq + 1) * 136 + j] = l01.y;
                Vl[(dq + 2) * 136 + j] = l23.x;
                Vl[(dq + 3) * 136 + j] = l23.y;
            }
        }
        asm volatile("cp.async.wait_group 0;" ::: "memory");
        __syncthreads();

        float S[16][4];
#pragma unroll
        for (int tn = 0; tn < 16; ++tn)
#pragma unroll
            for (int e = 0; e < 4; ++e) S[tn][e] = 0.f;
#pragma unroll
        for (int t2 = 0; t2 < 8; ++t2) {
#pragma unroll
            for (int kf = 0; kf < 4; ++kf) {
                uint32_t bh4[4], bl4[4];
                uint32_t off = (uint32_t)((t2 * 16 + arow) * 80 + kf * 16 + acg * 8) * 2;
                ldmx4(bh4, sKh + off);
                ldmx4(bl4, sKl + off);
#pragma unroll
                for (int sel = 0; sel < 2; ++sel) {
                    int tn = t2 * 2 + sel;
                    mma_bf(S[tn], quh[kf], bh4[sel], bh4[sel + 2]);
                    mma_bf(S[tn], qul[kf], bh4[sel], bh4[sel + 2]);
                    mma_bf(S[tn], quh[kf], bl4[sel], bl4[sel + 2]);
                }
            }
        }

        float mx[2] = {-1e30f, -1e30f};
#pragma unroll
        for (int tn = 0; tn < 16; ++tn) {
            int jc = j0 + tn * 8 + cq;
#pragma unroll
            for (int half = 0; half < 2; ++half) {
                int i = i0 + w * 16 + r_q + 8 * half;
                __half2 bh2 = *(const __half2*)&bd[((size_t)bh << 20) + ((size_t)i << 10) + jc];
                float2 bv = __half22float2(bh2);
                float v0 = (jc > i || jc >= len) ? -1e30f : (S[tn][half*2+0] + bv.x) * SCALE;
                float v1 = (jc + 1 > i || jc + 1 >= len) ? -1e30f : (S[tn][half*2+1] + bv.y) * SCALE;
                S[tn][half*2+0] = v0; S[tn][half*2+1] = v1;
                mx[half] = fmaxf(mx[half], fmaxf(v0, v1));
            }
        }
#pragma unroll
        for (int s = 1; s <= 2; s <<= 1) {
            mx[0] = fmaxf(mx[0], __shfl_xor_sync(0xFFFFFFFFu, mx[0], s));
            mx[1] = fmaxf(mx[1], __shfl_xor_sync(0xFFFFFFFFu, mx[1], s));
        }
        float newm[2], corr[2], rsum[2] = {0.f, 0.f};
#pragma unroll
        for (int half = 0; half < 2; ++half) {
            newm[half] = fmaxf(mrun[half], mx[half]);
            corr[half] = __expf(mrun[half] - newm[half]);
        }
#pragma unroll
        for (int tn = 0; tn < 16; ++tn)
#pragma unroll
            for (int half = 0; half < 2; ++half) {
                float p0 = __expf(S[tn][half*2+0] - newm[half]);
                float p1 = __expf(S[tn][half*2+1] - newm[half]);
                S[tn][half*2+0] = p0; S[tn][half*2+1] = p1;
                rsum[half] += p0 + p1;
            }
#pragma unroll
        for (int s = 1; s <= 2; s <<= 1) {
            rsum[0] += __shfl_xor_sync(0xFFFFFFFFu, rsum[0], s);
            rsum[1] += __shfl_xor_sync(0xFFFFFFFFu, rsum[1], s);
        }
#pragma unroll
        for (int half = 0; half < 2; ++half) {
            lrun[half] = lrun[half] * corr[half] + rsum[half];
            mrun[half] = newm[half];
        }
#pragma unroll
        for (int nf = 0; nf < 8; ++nf) {
            Of[nf][0] *= corr[0]; Of[nf][1] *= corr[0];
            Of[nf][2] *= corr[1]; Of[nf][3] *= corr[1];
        }
        uint32_t pfh[8][4], pfl[8][4];
#pragma unroll
        for (int kf = 0; kf < 8; ++kf) {
            float h0, h1, l0, l1;
            l0 = bflo(S[2*kf][0], &h0);  l1 = bflo(S[2*kf][1], &h1);
            pfh[kf][0] = packbf2(h0, h1); pfl[kf][0] = packbf2(l0, l1);
            l0 = bflo(S[2*kf][2], &h0);  l1 = bflo(S[2*kf][3], &h1);
            pfh[kf][1] = packbf2(h0, h1); pfl[kf][1] = packbf2(l0, l1);
            l0 = bflo(S[2*kf+1][0], &h0); l1 = bflo(S[2*kf+1][1], &h1);
            pfh[kf][2] = packbf2(h0, h1); pfl[kf][2] = packbf2(l0, l1);
            l0 = bflo(S[2*kf+1][2], &h0); l1 = bflo(S[2*kf+1][3], &h1);
            pfh[kf][3] = packbf2(h0, h1); pfl[kf][3] = packbf2(l0, l1);
        }
#pragma unroll
        for (int nf2 = 0; nf2 < 4; ++nf2) {
#pragma unroll
            for (int kf = 0; kf < 8; ++kf) {
                uint32_t vh4[4], vl4[4];
                uint32_t off = (uint32_t)((nf2 * 16 + arow) * 136 + kf * 16 + acg * 8) * 2;
                ldmx4(vh4, sVh + off);
                ldmx4(vl4, sVl + off);
#pragma unroll
                for (int sel = 0; sel < 2; ++sel) {
                    int nf = nf2 * 2 + sel;
                    mma_bf(Of[nf], pfh[kf], vh4[sel], vh4[sel + 2]);
                    mma_bf(Of[nf], pfl[kf], vh4[sel], vh4[sel + 2]);
                    mma_bf(Of[nf], pfh[kf], vl4[sel], vl4[sel + 2]);
                }
            }
        }
    }

    float inv[2] = {1.f / lrun[0], 1.f / lrun[1]};
#pragma unroll
    for (int nf = 0; nf < 8; ++nf)
#pragma unroll
        for (int half = 0; half < 2; ++half) {
            int i = i0 + w * 16 + r_q + 8 * half;
            int d = h * 64 + nf * 8 + cq;
            size_t o = (size_t)(b * TT + i) * DD + d;
            st_hf2(&Ta[o], Of[nf][half*2+0] * inv[half], Of[nf][half*2+1] * inv[half]);
        }
}

// ---------------- fp32 -> fp16 weight convert ------------------------------
__global__ void cvtw_kernel(const float* __restrict__ s, __half* __restrict__ d, int n)
{
    int idx = 4 * (blockIdx.x * 256 + threadIdx.x);
    if (idx >= n) return;
    float4 v = *(const float4*)&s[idx];
    st_hf2(&d[idx],     v.x, v.y);
    st_hf2(&d[idx + 2], v.z, v.w);
}

// ---------------- SIMT GEMM (embed + batched p) ----------------------------
#define BM 128
#define BN 128
#define BKK 16
__global__ __launch_bounds__(256) void gemm_kernel(
    const float* __restrict__ A, const float* __restrict__ W,
    const float* __restrict__ bias, float* __restrict__ C,
    __nv_bfloat16* __restrict__ Ph, __nv_bfloat16* __restrict__ Pl,
    int M, int N, int K)
{
    __shared__ float As[BKK][BM];
    __shared__ float Ws[BKK][BN];
    int tid = threadIdx.x;
    int tx = tid & 15, ty = tid >> 4;
    int m0 = blockIdx.y * BM, n0 = blockIdx.x * BN;
    int z = blockIdx.z;
    const float* Wz = W + (size_t)z * DD * DD;
    float acc[8][8];
#pragma unroll
    for (int e = 0; e < 8; e++)
#pragma unroll
        for (int f = 0; f < 8; f++) acc[e][f] = 0.f;
    for (int k0 = 0; k0 < K; k0 += BKK) {
#pragma unroll
        for (int i = 0; i < 8; i++) {
            int q = tid + i * 256;
            int r = q >> 4, kk = q & 15;
            As[kk][r] = A[(m0 + r) * K + k0 + kk];
            Ws[kk][r] = Wz[(n0 + r) * K + k0 + kk];
        }
        __syncthreads();
#pragma unroll
        for (int kk = 0; kk < BKK; kk++) {
            float a[8], wv[8];
#pragma unroll
            for (int e = 0; e < 8; e++) a[e] = As[kk][ty * 8 + e];
#pragma unroll
            for (int f = 0; f < 8; f++) wv[f] = Ws[kk][tx * 8 + f];
#pragma unroll
            for (int e = 0; e < 8; e++)
#pragma unroll
                for (int f = 0; f < 8; f++) acc[e][f] += a[e] * wv[f];
        }
        __syncthreads();
    }
#pragma unroll
    for (int e = 0; e < 8; e++) {
        int m = m0 + ty * 8 + e;
#pragma unroll
        for (int f = 0; f < 8; f++) {
            int n = n0 + tx * 8 + f;
            float v = acc[e][f];
            if (bias) v += bias[n];
            if (Ph) {
                int hq = n >> 6, dq = n & 63;
                size_t o = ((size_t)(z * HH + hq) << 16) + m * 64 + dq;
                float hi; float lo = bflo(v, &hi);
                Ph[o] = __float2bfloat16(hi);
                Pl[o] = __float2bfloat16(lo);
            } else {
                C[m * N + n] = v;
            }
        }
    }
}

// ---------------- BasicNorm (warp per row) + fp16 out ---------------------
__global__ __launch_bounds__(256) void norm_kernel(
    float* __restrict__ x, __half* __restrict__ xa)
{
    int row = blockIdx.x * 8 + (threadIdx.x >> 5);
    int lane = threadIdx.x & 31;
    float* p = x + (size_t)row * DD;
    float4 a = *(float4*)&p[lane * 8];
    float4 b = *(float4*)&p[lane * 8 + 4];
    float s = a.x*a.x + a.y*a.y + a.z*a.z + a.w*a.w
            + b.x*b.x + b.y*b.y + b.z*b.z + b.w*b.w;
#pragma unroll
    for (int o = 16; o > 0; o >>= 1) s += __shfl_xor_sync(0xFFFFFFFFu, s, o);
    float sc = rsqrtf(s * (1.f / DD) + EPSN);
    float vv[8] = {a.x*sc, a.y*sc, a.z*sc, a.w*sc, b.x*sc, b.y*sc, b.z*sc, b.w*sc};
    *(float4*)&p[lane * 8]     = make_float4(vv[0], vv[1], vv[2], vv[3]);
    *(float4*)&p[lane * 8 + 4] = make_float4(vv[4], vv[5], vv[6], vv[7]);
    size_t o = (size_t)row * DD + lane * 8;
#pragma unroll
    for (int q = 0; q < 8; q += 2) st_hf2(&xa[o + q], vv[q], vv[q+1]);
}

// ---------------- rel positional embedding --------------------------------
__global__ void pe_kernel(float* __restrict__ pe)
{
    int m = blockIdx.x;
    int c = threadIdx.x;
    int pos = (TT - 1) - m;
    int j = c >> 1;
    float div = expf((2.f * j) * (-9.210340371976184f / (float)DD));
    float ang = (float)pos * div;
    pe[m * DD + c] = (c & 1) ? cosf(ang) : sinf(ang);
}

// ---------------- output copy ---------------------------------------------
__global__ void output_kernel(const float* __restrict__ x,
                              const int* __restrict__ lens,
                              float* __restrict__ out, int out_size)
{
    int idx = blockIdx.x * 256 + threadIdx.x;
    if (idx >= out_size) return;
    if (idx < ROWS * DD) out[idx] = x[idx];
    else {
        int t = idx - ROWS * DD;
        out[idx] = (t < BB) ? (float)lens[t] : 0.f;
    }
}

// ============================ host driver =================================
extern "C" void kernel_launch(void* const* d_in, const int* in_sizes, int n_in,
                              void* d_out, int out_size)
{
    const float* x_in      = (const float*)d_in[0];
    const int*   lens      = (const int*)  d_in[1];
    const float* embed_W   = (const float*)d_in[2];
    const float* embed_b   = (const float*)d_in[3];
    const float* in_proj_W = (const float*)d_in[4];
    const float* in_proj_b = (const float*)d_in[5];
    const float* pos_W     = (const float*)d_in[6];
    const float* pos_u     = (const float*)d_in[7];
    const float* pos_v     = (const float*)d_in[8];
    const float* out_W     = (const float*)d_in[9];
    const float* out_b     = (const float*)d_in[10];
    const float* ff1_W     = (const float*)d_in[11];
    const float* ff1_b     = (const float*)d_in[12];
    const float* ff2_W     = (const float*)d_in[13];
    const float* ff2_b     = (const float*)d_in[14];

    float *gx, *gqkv, *gpe;
    __half *gbd;
    cudaGetSymbolAddress((void**)&gx,   g_x);
    cudaGetSymbolAddress((void**)&gqkv, g_qkv);
    cudaGetSymbolAddress((void**)&gpe,  g_pe);
    cudaGetSymbolAddress((void**)&gbd,  g_bd);
    __half *xa,*ta,*ha,*wq,*wo,*w1,*w2;
    __nv_bfloat16 *qvh,*qvl,*kh,*kl,*vh,*vl,*ph,*pl;
    cudaGetSymbolAddress((void**)&xa, g_xa);
    cudaGetSymbolAddress((void**)&ta, g_ta);
    cudaGetSymbolAddress((void**)&ha, g_ha);
    cudaGetSymbolAddress((void**)&wq, g_wqkv);
    cudaGetSymbolAddress((void**)&wo, g_wout);
    cudaGetSymbolAddress((void**)&w1, g_wf1);
    cudaGetSymbolAddress((void**)&w2, g_wf2);
    cudaGetSymbolAddress((void**)&qvh, g_qvh);   cudaGetSymbolAddress((void**)&qvl, g_qvl);
    cudaGetSymbolAddress((void**)&kh,  g_kh);    cudaGetSymbolAddress((void**)&kl,  g_kl);
    cudaGetSymbolAddress((void**)&vh,  g_vh);    cudaGetSymbolAddress((void**)&vl,  g_vl);
    cudaGetSymbolAddress((void**)&ph,  g_ph);    cudaGetSymbolAddress((void**)&pl,  g_pl);

    cudaFuncSetAttribute(mma_gemm<2>,  cudaFuncAttributeMaxDynamicSharedMemorySize, SMEM_MMA2);
    cudaFuncSetAttribute(mma_gemm<4>,  cudaFuncAttributeMaxDynamicSharedMemorySize, SMEM_MMA4);
    cudaFuncSetAttribute(bd_gemm,      cudaFuncAttributeMaxDynamicSharedMemorySize, BD_SMEM);
    cudaFuncSetAttribute(flash_kernel, cudaFuncAttributeMaxDynamicSharedMemorySize, FL_SMEM);

    // ---- launch order keeps 0-based index 3 == mma_gemm<2> (qkv layer 0)
    cvtw_kernel<<<(NL*3*DD*DD)/1024, 256>>>(in_proj_W, wq, NL*3*DD*DD);
    gemm_kernel<<<dim3(DD/BN, ROWS/BM), 256>>>(x_in, embed_W, embed_b, gx,
                                               nullptr, nullptr, ROWS, DD, DI);
    norm_kernel<<<ROWS/8, 256>>>(gx, xa);
    // 3: qkv layer 0  <-- ncu capture lands here
    mma_gemm<2><<<dim3(3*DD/128, ROWS/128), 256, SMEM_MMA2>>>(
        xa, wq, in_proj_b, nullptr, gqkv, nullptr,
        pos_v, qvh, qvl, kh, kl, vh, vl, DD, 3*DD, 3);
    pe_kernel<<<TT, DD>>>(gpe);
    // batched p for ALL layers
    gemm_kernel<<<dim3(DD/BN, TT/BM, NL), 256>>>(
        gpe, pos_W, nullptr, nullptr, ph, pl, TT, DD, DD);
    cvtw_kernel<<<(NL*DD*DD)/1024,   256>>>(out_W, wo, NL*DD*DD);
    cvtw_kernel<<<(NL*FFD*DD)/1024,  256>>>(ff1_W, w1, NL*FFD*DD);
    cvtw_kernel<<<(NL*DD*FFD)/1024,  256>>>(ff2_W, w2, NL*DD*FFD);

    for (int l = 0; l < NL; l++) {
        if (l > 0) {
            mma_gemm<2><<<dim3(3*DD/128, ROWS/128), 256, SMEM_MMA2>>>(
                xa, wq + (size_t)l*3*DD*DD, in_proj_b + l*3*DD, nullptr, gqkv, nullptr,
                pos_v + l*HH*DKK, qvh, qvl, kh, kl, vh, vl, DD, 3*DD, 3);
        }
        bd_gemm<<<dim3(TT/128, TT/128, BB*HH), 256, BD_SMEM>>>(
            qvh, qvl, ph + (size_t)l*HH*TT*DKK, pl + (size_t)l*HH*TT*DKK, gbd);
        flash_kernel<<<dim3(TT/128, BB*HH), 256, FL_SMEM>>>(
            gqkv, kh, kl, vh, vl, gbd, pos_u + l*HH*DKK, lens, ta);
        // out projection + residual -> x (+ xa fp16 for ff1)  [128x64 tiles]
        mma_gemm<4><<<dim3(DD/64, ROWS/128), 256, SMEM_MMA4>>>(
            ta, wo + (size_t)l*DD*DD, out_b + l*DD, gx, gx, xa,
            nullptr, nullptr, nullptr, nullptr, nullptr, nullptr, nullptr, DD, DD, 2);
        // FF1 + double_swish -> ha (fp16)
        mma_gemm<2><<<dim3(FFD/128, ROWS/128), 256, SMEM_MMA2>>>(
            xa, w1 + (size_t)l*FFD*DD, ff1_b + l*FFD, nullptr, nullptr, ha,
            nullptr, nullptr, nullptr, nullptr, nullptr, nullptr, nullptr, DD, FFD, 1);
        // FF2 + residual -> x  [128x64 tiles]
        mma_gemm<4><<<dim3(DD/64, ROWS/128), 256, SMEM_MMA4>>>(
            ha, w2 + (size_t)l*DD*FFD, ff2_b + l*DD, gx, gx, nullptr,
            nullptr, nullptr, nullptr, nullptr, nullptr, nullptr, nullptr, FFD, DD, 2);
        norm_kernel<<<ROWS/8, 256>>>(gx, xa);
    }

    output_kernel<<<(out_size + 255) / 256, 256>>>(gx, lens, (float*)d_out, out_size);
}

// round 16
// speedup vs baseline: 1.4019x; 1.1762x over previous
#include <cuda_runtime.h>
#include <cuda_bf16.h>
#include <cuda_fp16.h>
#include <math.h>
#include <stdint.h>

// Problem constants
#define BB 8
#define TT 1024
#define DI 80
#define DD 256
#define HH 4
#define DKK 64
#define FFD 2048
#define NL 6
#define ROWS (BB*TT)        // 8192
#define SCALE 0.125f
#define EPSN 0.25f

// -------- scratch (static device globals) ----------
__device__ float g_x[ROWS*DD];
__device__ float g_qkv[ROWS*3*DD];      // only Q third written/read
__device__ float g_pe[TT*DD];
__device__ __half g_bd[BB*HH*TT*TT];    // pre-shifted rel-pos term (fp16)

// fp16 activation buffers
__device__ __half g_xa[ROWS*DD];
__device__ __half g_ta[ROWS*DD];
__device__ __half g_ha[ROWS*FFD];
// fp16 weights
__device__ __half g_wqkv[NL*3*DD*DD];
__device__ __half g_wout[NL*DD*DD];
__device__ __half g_wf1[NL*FFD*DD];
__device__ __half g_wf2[NL*DD*FFD];
// fp16 attention buffers (single precision)
__device__ __half g_qv[BB*HH*TT*DKK];
__device__ __half g_k[BB*HH*TT*DKK];
__device__ __half g_v[BB*HH*TT*DKK];
__device__ __half g_p[NL*HH*TT*DKK];

// ===================== PTX helpers (arch-neutral, sm_80+) =================
__device__ __forceinline__ uint32_t smem_u32(const void* p) {
    uint32_t a;
    asm("{ .reg .u64 t; cvta.to.shared.u64 t, %1; cvt.u32.u64 %0, t; }" : "=r"(a) : "l"(p));
    return a;
}
#define CP_ASYNC16(sa, ga) asm volatile("cp.async.cg.shared.global [%0], [%1], 16;" :: "r"(sa), "l"(ga))
#define CP_COMMIT()        asm volatile("cp.async.commit_group;" ::: "memory")

__device__ __forceinline__ void ldmx4(uint32_t (&r)[4], uint32_t addr) {
    asm volatile("ldmatrix.sync.aligned.m8n8.x4.shared.b16 {%0,%1,%2,%3}, [%4];"
        : "=r"(r[0]), "=r"(r[1]), "=r"(r[2]), "=r"(r[3]) : "r"(addr));
}
__device__ __forceinline__ void mma_hf(float (&c)[4], const uint32_t (&a)[4],
                                       uint32_t b0, uint32_t b1) {
    asm volatile("mma.sync.aligned.m16n8k16.row.col.f32.f16.f16.f32 "
        "{%0,%1,%2,%3}, {%4,%5,%6,%7}, {%8,%9}, {%0,%1,%2,%3};"
        : "+f"(c[0]), "+f"(c[1]), "+f"(c[2]), "+f"(c[3])
        : "r"(a[0]), "r"(a[1]), "r"(a[2]), "r"(a[3]), "r"(b0), "r"(b1));
}
__device__ __forceinline__ uint32_t packh2(float a, float b) {
    __half2 t = __floats2half2_rn(a, b);
    return *(uint32_t*)&t;
}
__device__ __forceinline__ void st_hf2(__half* p, float a, float b) {
    *(__half2*)p = __floats2half2_rn(a, b);
}

// ===================== fp16 mma.sync GEMM (linear layers) =================
#define PADK 72

template<int WM>
__global__ __launch_bounds__(256, 2) void mma_gemm(
    const __half* __restrict__ A, const __half* __restrict__ B,
    const float* __restrict__ bias, const float* __restrict__ resid,
    float* __restrict__ C, __half* __restrict__ Oa,
    const float* __restrict__ pvb,
    __half* __restrict__ Qv, __half* __restrict__ Kk, __half* __restrict__ Vv,
    int K, int ldC, int ep)
{
    constexpr int NT     = (8 / WM) * 32;
    constexpr int TMW    = 128 / (WM * 16);
    constexpr int ATILE_E = 128 * PADK;
    constexpr int BTILE_E = NT * PADK;
    constexpr int STG    = (ATILE_E + BTILE_E) * 2;

    extern __shared__ __half sm[];
    int tid = threadIdx.x, lane = tid & 31, w = tid >> 5;
    int wm = w % WM, wn = w / WM;
    int m0 = blockIdx.y * 128, n0 = blockIdx.x * NT;
    const __half* gA = A + (size_t)m0 * K;
    const __half* gB = B + (size_t)n0 * K;

    float acc[TMW][4][4];
#pragma unroll
    for (int a = 0; a < TMW; a++)
#pragma unroll
        for (int b = 0; b < 4; b++)
#pragma unroll
            for (int c = 0; c < 4; c++) acc[a][b][c] = 0.f;

    uint32_t sbase0 = smem_u32(sm);
    int nch = K >> 6;

    auto issue = [&](int c) {
        uint32_t sb = sbase0 + (uint32_t)(c & 1) * STG;
        int k0 = c * 64;
#pragma unroll
        for (int i = 0; i < 4; ++i) {
            int q = tid + i * 256;
            int r = q >> 3, c16 = q & 7;
            CP_ASYNC16(sb + (uint32_t)(r * PADK + c16 * 8) * 2,
                       gA + (size_t)r * K + k0 + c16 * 8);
        }
#pragma unroll
        for (int i = 0; i < NT / 32; ++i) {
            int q = tid + i * 256;
            int r = q >> 3, c16 = q & 7;
            CP_ASYNC16(sb + (uint32_t)(ATILE_E + r * PADK + c16 * 8) * 2,
                       gB + (size_t)r * K + k0 + c16 * 8);
        }
        CP_COMMIT();
    };

    issue(0);
    for (int c = 0; c < nch; ++c) {
        if (c + 1 < nch) {
            issue(c + 1);
            asm volatile("cp.async.wait_group 1;" ::: "memory");
        } else {
            asm volatile("cp.async.wait_group 0;" ::: "memory");
        }
        __syncthreads();
        uint32_t sb = sbase0 + (uint32_t)(c & 1) * STG;
        uint32_t sA = sb, sB = sb + ATILE_E * 2;
        int arow = lane & 15, acg = lane >> 4;
#pragma unroll
        for (int kh = 0; kh < 4; ++kh) {
            int kb = kh * 16;
            uint32_t af[TMW][4], bf[2][4];
#pragma unroll
            for (int tm = 0; tm < TMW; ++tm) {
                uint32_t off = (uint32_t)((wm * (TMW * 16) + tm * 16 + arow) * PADK + kb + acg * 8) * 2;
                ldmx4(af[tm], sA + off);
            }
#pragma unroll
            for (int t2 = 0; t2 < 2; ++t2) {
                uint32_t off = (uint32_t)((wn * 32 + t2 * 16 + arow) * PADK + kb + acg * 8) * 2;
                ldmx4(bf[t2], sB + off);
            }
#pragma unroll
            for (int tm = 0; tm < TMW; ++tm)
#pragma unroll
                for (int tn = 0; tn < 4; ++tn) {
                    int t2 = tn >> 1, sel = tn & 1;
                    mma_hf(acc[tm][tn], af[tm], bf[t2][sel], bf[t2][sel + 2]);
                }
        }
        __syncthreads();
    }

    int mrow = lane >> 2, ncol = (lane & 3) * 2;
#pragma unroll
    for (int tm = 0; tm < TMW; ++tm) {
#pragma unroll
        for (int tn = 0; tn < 4; ++tn) {
            int n = n0 + wn * 32 + tn * 8 + ncol;
            float2 bs = *(const float2*)&bias[n];
#pragma unroll
            for (int half = 0; half < 2; ++half) {
                int mm = m0 + wm * (TMW * 16) + tm * 16 + mrow + half * 8;
                float v0 = acc[tm][tn][half * 2 + 0] + bs.x;
                float v1 = acc[tm][tn][half * 2 + 1] + bs.y;
                size_t o = (size_t)mm * ldC + n;
                if (ep == 0 || ep == 3) {
                    if (ep == 0 || n < DD)
                        *(float2*)&C[o] = make_float2(v0, v1);
                    if (ep == 3) {
                        int bq = mm >> 10, iq = mm & 1023;
                        int hq = (n >> 6) & 3, dq = n & 63;
                        size_t qo = ((size_t)(bq * 4 + hq) << 16) + iq * 64 + dq;
                        if (n < DD) {
                            st_hf2(&Qv[qo], v0 + pvb[n], v1 + pvb[n + 1]);
                        } else if (n < 2 * DD) {
                            st_hf2(&Kk[qo], v0, v1);
                        } else {
                            st_hf2(&Vv[qo], v0, v1);
                        }
                    }
                } else if (ep == 1) {
                    v0 = v0 / (1.f + expf(1.f - v0));
                    v1 = v1 / (1.f + expf(1.f - v1));
                    st_hf2(&Oa[o], v0, v1);
                } else {
                    float2 rs = *(const float2*)&resid[o];
                    v0 += rs.x; v1 += rs.y;
                    *(float2*)&C[o] = make_float2(v0, v1);
                    if (Oa) st_hf2(&Oa[o], v0, v1);
                }
            }
        }
    }
}

#define SMEM_MMA2 (2*((128*PADK)+(128*PADK))*2)   // 73728
#define SMEM_MMA4 (2*((128*PADK)+(64*PADK))*2)    // 55296

// ===================== bd_gemm: shifted rel-pos GEMM (fp16) ===============
#define BD_SMEM (2*128*80*2)   // 40960
__global__ __launch_bounds__(256, 2) void bd_gemm(
    const __half* __restrict__ qv, const __half* __restrict__ p,
    __half* __restrict__ bd)
{
    int mt = blockIdx.x, it = blockIdx.y, bh = blockIdx.z;
    int i0 = it * 128, m0 = mt * 128;
    if (i0 + m0 + 254 < TT - 1) return;
    int h = bh & 3;

    extern __shared__ __half bsm[];
    __half* Aq = bsm;              // [128][80]
    __half* Bp = Aq + 128*80;
    int tid = threadIdx.x, lane = tid & 31, w = tid >> 5;
    int wm = w & 1, wn = w >> 1;

    const __half* srcA = qv + ((size_t)bh << 16) + i0 * 64;
    const __half* srcB = p  + ((size_t)h  << 16) + m0 * 64;
#pragma unroll
    for (int i = 0; i < 4; ++i) {
        int idx = tid + i * 256;
        int r = idx >> 3, c8 = idx & 7;
        *(uint4*)&Aq[r*80 + c8*8] = *(const uint4*)&srcA[r*64 + c8*8];
        *(uint4*)&Bp[r*80 + c8*8] = *(const uint4*)&srcB[r*64 + c8*8];
    }
    __syncthreads();

    uint32_t sA = smem_u32(Aq), sB = smem_u32(Bp);
    float acc[4][4][4];
#pragma unroll
    for (int a = 0; a < 4; a++)
#pragma unroll
        for (int b = 0; b < 4; b++)
#pragma unroll
            for (int c = 0; c < 4; c++) acc[a][b][c] = 0.f;

    int arow = lane & 15, acg = lane >> 4;
#pragma unroll
    for (int kf = 0; kf < 4; ++kf) {
        int kb = kf * 16;
        uint32_t af[4][4], bf[2][4];
#pragma unroll
        for (int tm = 0; tm < 4; ++tm) {
            uint32_t off = (uint32_t)((wm * 64 + tm * 16 + arow) * 80 + kb + acg * 8) * 2;
            ldmx4(af[tm], sA + off);
        }
#pragma unroll
        for (int t2 = 0; t2 < 2; ++t2) {
            uint32_t off = (uint32_t)((wn * 32 + t2 * 16 + arow) * 80 + kb + acg * 8) * 2;
            ldmx4(bf[t2], sB + off);
        }
#pragma unroll
        for (int tm = 0; tm < 4; ++tm)
#pragma unroll
            for (int tn = 0; tn < 4; ++tn) {
                int t2 = tn >> 1, sel = tn & 1;
                mma_hf(acc[tm][tn], af[tm], bf[t2][sel], bf[t2][sel + 2]);
            }
    }

    int mrow = lane >> 2, ncol = (lane & 3) * 2;
#pragma unroll
    for (int tm = 0; tm < 4; ++tm)
#pragma unroll
        for (int tn = 0; tn < 4; ++tn)
#pragma unroll
            for (int half = 0; half < 2; ++half) {
                int i = i0 + wm * 64 + tm * 16 + mrow + half * 8;
                int m = m0 + wn * 32 + tn * 8 + ncol;
#pragma unroll
                for (int e = 0; e < 2; ++e) {
                    int j = m + e + i - (TT - 1);
                    if (j >= 0 && j <= i)
                        bd[((size_t)bh << 20) + ((size_t)i << 10) + j] =
                            __float2half_rn(acc[tm][tn][half * 2 + e]);
                }
            }
}

// ===================== fused flash attention (fp16) =======================
#define FL_SMEM (128*80*2 + 64*136*2)   // 37888
__global__ __launch_bounds__(256, 2) void flash_kernel(
    const float* __restrict__ qkv,
    const __half* __restrict__ KG, const __half* __restrict__ VG,
    const __half* __restrict__ bd,
    const float* __restrict__ ub_all, const int* __restrict__ lens,
    __half* __restrict__ Ta)
{
    extern __shared__ __half fsm[];
    __half* Ks = fsm;               // [128][80]
    __half* Vs = Ks + 128*80;       // [64][136]  (V transposed)
    uint32_t sK = smem_u32(Ks), sV = smem_u32(Vs);

    int tid = threadIdx.x, lane = tid & 31, w = tid >> 5;
    int bh = blockIdx.y, b = bh >> 2, h = bh & 3;
    int i0 = ((int)gridDim.x - 1 - (int)blockIdx.x) * 128;
    int len = lens[b];
    int arow = lane & 15, acg = lane >> 4;
    int r_q = lane >> 2, cq = (lane & 3) * 2;
    size_t kvbase = ((size_t)bh << 16);

    // ---- stage QU (q + u) into K smem, load A-frags to regs
    {
        int d4 = (tid & 15) * 4, r0 = tid >> 4;
        float4 uu = *(const float4*)&ub_all[h * DKK + d4];
#pragma unroll
        for (int it = 0; it < 8; ++it) {
            int r = r0 + it * 16;
            float4 v = *(const float4*)&qkv[((size_t)(b * TT + i0 + r)) * 768 + h * 64 + d4];
            Ks[r * 80 + d4 + 0] = __float2half_rn(v.x + uu.x);
            Ks[r * 80 + d4 + 1] = __float2half_rn(v.y + uu.y);
            Ks[r * 80 + d4 + 2] = __float2half_rn(v.z + uu.z);
            Ks[r * 80 + d4 + 3] = __float2half_rn(v.w + uu.w);
        }
    }
    __syncthreads();
    uint32_t qu[4][4];
#pragma unroll
    for (int kf = 0; kf < 4; ++kf) {
        uint32_t off = (uint32_t)((w * 16 + arow) * 80 + kf * 16 + acg * 8) * 2;
        ldmx4(qu[kf], sK + off);
    }

    float Of[8][4];
#pragma unroll
    for (int nf = 0; nf < 8; ++nf)
#pragma unroll
        for (int e = 0; e < 4; ++e) Of[nf][e] = 0.f;
    float mrun[2] = {-1e30f, -1e30f}, lrun[2] = {0.f, 0.f};

    for (int j0 = 0; j0 <= i0; j0 += 128) {
        __syncthreads();
        // ---- K tile via cp.async (fp16)
#pragma unroll
        for (int i2 = 0; i2 < 4; ++i2) {
            int idx = tid + i2 * 256;
            int r = idx >> 3, c8 = idx & 7;
            CP_ASYNC16(sK + (uint32_t)(r * 80 + c8 * 8) * 2,
                       &KG[kvbase + (size_t)(j0 + r) * 64 + c8 * 8]);
        }
        CP_COMMIT();
        // ---- V transposed staging (fp16)
        {
            int jj0 = tid & 15, dq = (tid >> 4) * 4;
#pragma unroll
            for (int it = 0; it < 8; ++it) {
                int j = jj0 + it * 16;
                uint2 rv = *(const uint2*)&VG[kvbase + (size_t)(j0 + j) * 64 + dq];
                __half2 v01 = *(__half2*)&rv.x;
                __half2 v23 = *(__half2*)&rv.y;
                Vs[(dq + 0) * 136 + j] = v01.x;
                Vs[(dq + 1) * 136 + j] = v01.y;
                Vs[(dq + 2) * 136 + j] = v23.x;
                Vs[(dq + 3) * 136 + j] = v23.y;
            }
        }
        asm volatile("cp.async.wait_group 0;" ::: "memory");
        __syncthreads();

        // ---- S = QU @ K^T (fp16)
        float S[16][4];
#pragma unroll
        for (int tn = 0; tn < 16; ++tn)
#pragma unroll
            for (int e = 0; e < 4; ++e) S[tn][e] = 0.f;
#pragma unroll
        for (int t2 = 0; t2 < 8; ++t2) {
#pragma unroll
            for (int kf = 0; kf < 4; ++kf) {
                uint32_t bk[4];
                uint32_t off = (uint32_t)((t2 * 16 + arow) * 80 + kf * 16 + acg * 8) * 2;
                ldmx4(bk, sK + off);
#pragma unroll
                for (int sel = 0; sel < 2; ++sel)
                    mma_hf(S[t2 * 2 + sel], qu[kf], bk[sel], bk[sel + 2]);
            }
        }

        float mx[2] = {-1e30f, -1e30f};
#pragma unroll
        for (int tn = 0; tn < 16; ++tn) {
            int jc = j0 + tn * 8 + cq;
#pragma unroll
            for (int half = 0; half < 2; ++half) {
                int i = i0 + w * 16 + r_q + 8 * half;
                __half2 bh2 = *(const __half2*)&bd[((size_t)bh << 20) + ((size_t)i << 10) + jc];
                float2 bv = __half22float2(bh2);
                float v0 = (jc > i || jc >= len) ? -1e30f : (S[tn][half*2+0] + bv.x) * SCALE;
                float v1 = (jc + 1 > i || jc + 1 >= len) ? -1e30f : (S[tn][half*2+1] + bv.y) * SCALE;
                S[tn][half*2+0] = v0; S[tn][half*2+1] = v1;
                mx[half] = fmaxf(mx[half], fmaxf(v0, v1));
            }
        }
#pragma unroll
        for (int s = 1; s <= 2; s <<= 1) {
            mx[0] = fmaxf(mx[0], __shfl_xor_sync(0xFFFFFFFFu, mx[0], s));
            mx[1] = fmaxf(mx[1], __shfl_xor_sync(0xFFFFFFFFu, mx[1], s));
        }
        float newm[2], corr[2], rsum[2] = {0.f, 0.f};
#pragma unroll
        for (int half = 0; half < 2; ++half) {
            newm[half] = fmaxf(mrun[half], mx[half]);
            corr[half] = __expf(mrun[half] - newm[half]);
        }
#pragma unroll
        for (int tn = 0; tn < 16; ++tn)
#pragma unroll
            for (int half = 0; half < 2; ++half) {
                float p0 = __expf(S[tn][half*2+0] - newm[half]);
                float p1 = __expf(S[tn][half*2+1] - newm[half]);
                S[tn][half*2+0] = p0; S[tn][half*2+1] = p1;
                rsum[half] += p0 + p1;
            }
#pragma unroll
        for (int s = 1; s <= 2; s <<= 1) {
            rsum[0] += __shfl_xor_sync(0xFFFFFFFFu, rsum[0], s);
            rsum[1] += __shfl_xor_sync(0xFFFFFFFFu, rsum[1], s);
        }
#pragma unroll
        for (int half = 0; half < 2; ++half) {
            lrun[half] = lrun[half] * corr[half] + rsum[half];
            mrun[half] = newm[half];
        }
#pragma unroll
        for (int nf = 0; nf < 8; ++nf) {
            Of[nf][0] *= corr[0]; Of[nf][1] *= corr[0];
            Of[nf][2] *= corr[1]; Of[nf][3] *= corr[1];
        }
        // ---- build P fp16 A-frags from S (registers only)
        uint32_t pf[8][4];
#pragma unroll
        for (int kf = 0; kf < 8; ++kf) {
            pf[kf][0] = packh2(S[2*kf][0],   S[2*kf][1]);
            pf[kf][1] = packh2(S[2*kf][2],   S[2*kf][3]);
            pf[kf][2] = packh2(S[2*kf+1][0], S[2*kf+1][1]);
            pf[kf][3] = packh2(S[2*kf+1][2], S[2*kf+1][3]);
        }
        // ---- O += P @ V (fp16)
#pragma unroll
        for (int nf2 = 0; nf2 < 4; ++nf2) {
#pragma unroll
            for (int kf = 0; kf < 8; ++kf) {
                uint32_t v4[4];
                uint32_t off = (uint32_t)((nf2 * 16 + arow) * 136 + kf * 16 + acg * 8) * 2;
                ldmx4(v4, sV + off);
#pragma unroll
                for (int sel = 0; sel < 2; ++sel)
                    mma_hf(Of[nf2 * 2 + sel], pf[kf], v4[sel], v4[sel + 2]);
            }
        }
    }

    float inv[2] = {1.f / lrun[0], 1.f / lrun[1]};
#pragma unroll
    for (int nf = 0; nf < 8; ++nf)
#pragma unroll
        for (int half = 0; half < 2; ++half) {
            int i = i0 + w * 16 + r_q + 8 * half;
            int d = h * 64 + nf * 8 + cq;
            size_t o = (size_t)(b * TT + i) * DD + d;
            st_hf2(&Ta[o], Of[nf][half*2+0] * inv[half], Of[nf][half*2+1] * inv[half]);
        }
}

// ---------------- fp32 -> fp16 weight convert ------------------------------
__global__ void cvtw_kernel(const float* __restrict__ s, __half* __restrict__ d, int n)
{
    int idx = 4 * (blockIdx.x * 256 + threadIdx.x);
    if (idx >= n) return;
    float4 v = *(const float4*)&s[idx];
    st_hf2(&d[idx],     v.x, v.y);
    st_hf2(&d[idx + 2], v.z, v.w);
}

// ---------------- SIMT GEMM (embed + batched p) ----------------------------
#define BM 128
#define BN 128
#define BKK 16
__global__ __launch_bounds__(256) void gemm_kernel(
    const float* __restrict__ A, const float* __restrict__ W,
    const float* __restrict__ bias, float* __restrict__ C,
    __half* __restrict__ Ph,
    int M, int N, int K)
{
    __shared__ float As[BKK][BM];
    __shared__ float Ws[BKK][BN];
    int tid = threadIdx.x;
    int tx = tid & 15, ty = tid >> 4;
    int m0 = blockIdx.y * BM, n0 = blockIdx.x * BN;
    int z = blockIdx.z;
    const float* Wz = W + (size_t)z * DD * DD;
    float acc[8][8];
#pragma unroll
    for (int e = 0; e < 8; e++)
#pragma unroll
        for (int f = 0; f < 8; f++) acc[e][f] = 0.f;
    for (int k0 = 0; k0 < K; k0 += BKK) {
#pragma unroll
        for (int i = 0; i < 8; i++) {
            int q = tid + i * 256;
            int r = q >> 4, kk = q & 15;
            As[kk][r] = A[(m0 + r) * K + k0 + kk];
            Ws[kk][r] = Wz[(n0 + r) * K + k0 + kk];
        }
        __syncthreads();
#pragma unroll
        for (int kk = 0; kk < BKK; kk++) {
            float a[8], wv[8];
#pragma unroll
            for (int e = 0; e < 8; e++) a[e] = As[kk][ty * 8 + e];
#pragma unroll
            for (int f = 0; f < 8; f++) wv[f] = Ws[kk][tx * 8 + f];
#pragma unroll
            for (int e = 0; e < 8; e++)
#pragma unroll
                for (int f = 0; f < 8; f++) acc[e][f] += a[e] * wv[f];
        }
        __syncthreads();
    }
#pragma unroll
    for (int e = 0; e < 8; e++) {
        int m = m0 + ty * 8 + e;
#pragma unroll
        for (int f = 0; f < 8; f++) {
            int n = n0 + tx * 8 + f;
            float v = acc[e][f];
            if (bias) v += bias[n];
            if (Ph) {
                int hq = n >> 6, dq = n & 63;
                size_t o = ((size_t)(z * HH + hq) << 16) + m * 64 + dq;
                Ph[o] = __float2half_rn(v);
            } else {
                C[m * N + n] = v;
            }
        }
    }
}

// ---------------- BasicNorm (warp per row) + fp16 out ---------------------
__global__ __launch_bounds__(256) void norm_kernel(
    float* __restrict__ x, __half* __restrict__ xa)
{
    int row = blockIdx.x * 8 + (threadIdx.x >> 5);
    int lane = threadIdx.x & 31;
    float* p = x + (size_t)row * DD;
    float4 a = *(float4*)&p[lane * 8];
    float4 b = *(float4*)&p[lane * 8 + 4];
    float s = a.x*a.x + a.y*a.y + a.z*a.z + a.w*a.w
            + b.x*b.x + b.y*b.y + b.z*b.z + b.w*b.w;
#pragma unroll
    for (int o = 16; o > 0; o >>= 1) s += __shfl_xor_sync(0xFFFFFFFFu, s, o);
    float sc = rsqrtf(s * (1.f / DD) + EPSN);
    float vv[8] = {a.x*sc, a.y*sc, a.z*sc, a.w*sc, b.x*sc, b.y*sc, b.z*sc, b.w*sc};
    *(float4*)&p[lane * 8]     = make_float4(vv[0], vv[1], vv[2], vv[3]);
    *(float4*)&p[lane * 8 + 4] = make_float4(vv[4], vv[5], vv[6], vv[7]);
    size_t o = (size_t)row * DD + lane * 8;
#pragma unroll
    for (int q = 0; q < 8; q += 2) st_hf2(&xa[o + q], vv[q], vv[q+1]);
}

// ---------------- rel positional embedding --------------------------------
__global__ void pe_kernel(float* __restrict__ pe)
{
    int m = blockIdx.x;
    int c = threadIdx.x;
    int pos = (TT - 1) - m;
    int j = c >> 1;
    float div = expf((2.f * j) * (-9.210340371976184f / (float)DD));
    float ang = (float)pos * div;
    pe[m * DD + c] = (c & 1) ? cosf(ang) : sinf(ang);
}

// ---------------- output copy ---------------------------------------------
__global__ void output_kernel(const float* __restrict__ x,
                              const int* __restrict__ lens,
                              float* __restrict__ out, int out_size)
{
    int idx = blockIdx.x * 256 + threadIdx.x;
    if (idx >= out_size) return;
    if (idx < ROWS * DD) out[idx] = x[idx];
    else {
        int t = idx - ROWS * DD;
        out[idx] = (t < BB) ? (float)lens[t] : 0.f;
    }
}

// ============================ host driver =================================
extern "C" void kernel_launch(void* const* d_in, const int* in_sizes, int n_in,
                              void* d_out, int out_size)
{
    const float* x_in      = (const float*)d_in[0];
    const int*   lens      = (const int*)  d_in[1];
    const float* embed_W   = (const float*)d_in[2];
    const float* embed_b   = (const float*)d_in[3];
    const float* in_proj_W = (const float*)d_in[4];
    const float* in_proj_b = (const float*)d_in[5];
    const float* pos_W     = (const float*)d_in[6];
    const float* pos_u     = (const float*)d_in[7];
    const float* pos_v     = (const float*)d_in[8];
    const float* out_W     = (const float*)d_in[9];
    const float* out_b     = (const float*)d_in[10];
    const float* ff1_W     = (const float*)d_in[11];
    const float* ff1_b     = (const float*)d_in[12];
    const float* ff2_W     = (const float*)d_in[13];
    const float* ff2_b     = (const float*)d_in[14];

    float *gx, *gqkv, *gpe;
    __half *gbd;
    cudaGetSymbolAddress((void**)&gx,   g_x);
    cudaGetSymbolAddress((void**)&gqkv, g_qkv);
    cudaGetSymbolAddress((void**)&gpe,  g_pe);
    cudaGetSymbolAddress((void**)&gbd,  g_bd);
    __half *xa,*ta,*ha,*wq,*wo,*w1,*w2,*qv,*kk,*vv,*pp;
    cudaGetSymbolAddress((void**)&xa, g_xa);
    cudaGetSymbolAddress((void**)&ta, g_ta);
    cudaGetSymbolAddress((void**)&ha, g_ha);
    cudaGetSymbolAddress((void**)&wq, g_wqkv);
    cudaGetSymbolAddress((void**)&wo, g_wout);
    cudaGetSymbolAddress((void**)&w1, g_wf1);
    cudaGetSymbolAddress((void**)&w2, g_wf2);
    cudaGetSymbolAddress((void**)&qv, g_qv);
    cudaGetSymbolAddress((void**)&kk, g_k);
    cudaGetSymbolAddress((void**)&vv, g_v);
    cudaGetSymbolAddress((void**)&pp, g_p);

    cudaFuncSetAttribute(mma_gemm<2>,  cudaFuncAttributeMaxDynamicSharedMemorySize, SMEM_MMA2);
    cudaFuncSetAttribute(mma_gemm<4>,  cudaFuncAttributeMaxDynamicSharedMemorySize, SMEM_MMA4);
    cudaFuncSetAttribute(bd_gemm,      cudaFuncAttributeMaxDynamicSharedMemorySize, BD_SMEM);
    cudaFuncSetAttribute(flash_kernel, cudaFuncAttributeMaxDynamicSharedMemorySize, FL_SMEM);

    // ---- launch order keeps 0-based index 3 == mma_gemm<2> (qkv layer 0)
    cvtw_kernel<<<(NL*3*DD*DD)/1024, 256>>>(in_proj_W, wq, NL*3*DD*DD);
    gemm_kernel<<<dim3(DD/BN, ROWS/BM), 256>>>(x_in, embed_W, embed_b, gx,
                                               nullptr, ROWS, DD, DI);
    norm_kernel<<<ROWS/8, 256>>>(gx, xa);
    // 3: qkv layer 0  <-- ncu capture lands here
    mma_gemm<2><<<dim3(3*DD/128, ROWS/128), 256, SMEM_MMA2>>>(
        xa, wq, in_proj_b, nullptr, gqkv, nullptr,
        pos_v, qv, kk, vv, DD, 3*DD, 3);
    pe_kernel<<<TT, DD>>>(gpe);
    // batched p for ALL layers (fp16 out)
    gemm_kernel<<<dim3(DD/BN, TT/BM, NL), 256>>>(
        gpe, pos_W, nullptr, nullptr, pp, TT, DD, DD);
    cvtw_kernel<<<(NL*DD*DD)/1024,   256>>>(out_W, wo, NL*DD*DD);
    cvtw_kernel<<<(NL*FFD*DD)/1024,  256>>>(ff1_W, w1, NL*FFD*DD);
    cvtw_kernel<<<(NL*DD*FFD)/1024,  256>>>(ff2_W, w2, NL*DD*FFD);

    for (int l = 0; l < NL; l++) {
        if (l > 0) {
            mma_gemm<2><<<dim3(3*DD/128, ROWS/128), 256, SMEM_MMA2>>>(
                xa, wq + (size_t)l*3*DD*DD, in_proj_b + l*3*DD, nullptr, gqkv, nullptr,
                pos_v + l*HH*DKK, qv, kk, vv, DD, 3*DD, 3);
        }
        bd_gemm<<<dim3(TT/128, TT/128, BB*HH), 256, BD_SMEM>>>(
            qv, pp + (size_t)l*HH*TT*DKK, gbd);
        flash_kernel<<<dim3(TT/128, BB*HH), 256, FL_SMEM>>>(
            gqkv, kk, vv, gbd, pos_u + l*HH*DKK, lens, ta);
        // out projection + residual -> x (+ xa fp16 for ff1)  [128x64 tiles]
        mma_gemm<4><<<dim3(DD/64, ROWS/128), 256, SMEM_MMA4>>>(
            ta, wo + (size_t)l*DD*DD, out_b + l*DD, gx, gx, xa,
            nullptr, nullptr, nullptr, nullptr, DD, DD, 2);
        // FF1 + double_swish -> ha (fp16)
        mma_gemm<2><<<dim3(FFD/128, ROWS/128), 256, SMEM_MMA2>>>(
            xa, w1 + (size_t)l*FFD*DD, ff1_b + l*FFD, nullptr, nullptr, ha,
            nullptr, nullptr, nullptr, nullptr, DD, FFD, 1);
        // FF2 + residual -> x  [128x64 tiles]
        mma_gemm<4><<<dim3(DD/64, ROWS/128), 256, SMEM_MMA4>>>(
            ha, w2 + (size_t)l*DD*FFD, ff2_b + l*DD, gx, gx, nullptr,
            nullptr, nullptr, nullptr, nullptr, FFD, DD, 2);
        norm_kernel<<<ROWS/8, 256>>>(gx, xa);
    }

    output_kernel<<<(out_size + 255) / 256, 256>>>(gx, lens, (float*)d_out, out_size);
}